// round 2
// baseline (speedup 1.0000x reference)
#include <cuda_runtime.h>
#include <cuda_bf16.h>
#include <math.h>

// ---------------- problem constants ----------------
#define LAYERS 2
#define Dm     512
#define Hh     8
#define DHh    64
#define Mff    2048
#define O0     132
#define O1     3
#define Bb     2
#define Tt     2048
#define ROWS   (Bb*Tt)          // 4096
#define QKVW   (3*Hh*DHh)       // 1536
#define CAT0   648              // 644 padded to mult of 8
#define CAT1   520              // 515 padded to mult of 8

// ---------------- scratch (device globals, no allocs) ----------------
__device__ __align__(128) float g_x  [ROWS * Dm];
__device__ __align__(128) float g_h  [ROWS * Dm];
__device__ __align__(128) float g_qkv[ROWS * QKVW];
__device__ __align__(128) float g_att[ROWS * Dm];
__device__ __align__(128) float g_ff [ROWS * Mff];
__device__ __align__(128) float g_cat[ROWS * CAT0];
__device__ __align__(128) float g_y0 [ROWS * O0];
__device__ __align__(128) float g_y1 [ROWS * O1];

// ---------------- helpers ----------------
__device__ __forceinline__ float gelu_exact(float x) {
    return 0.5f * x * (1.0f + erff(x * 0.70710678118654752f));
}

// ---------------- elementwise copy ----------------
__global__ void copy_kernel(const float* __restrict__ src, float* __restrict__ dst, int n) {
    int i = blockIdx.x * blockDim.x + threadIdx.x;
    int stride = gridDim.x * blockDim.x;
    for (; i < n; i += stride) dst[i] = src[i];
}

// ---------------- layernorm: row of 512, block 256 ----------------
__global__ __launch_bounds__(256) void ln_kernel(
    const float* __restrict__ x, const float* __restrict__ g,
    const float* __restrict__ bta, float* __restrict__ out)
{
    __shared__ float red[256];
    int r = blockIdx.x, tid = threadIdx.x;
    float2 v = ((const float2*)(x + (size_t)r * Dm))[tid];
    red[tid] = v.x + v.y;
    __syncthreads();
    for (int off = 128; off; off >>= 1) {
        if (tid < off) red[tid] += red[tid + off];
        __syncthreads();
    }
    float mean = red[0] * (1.0f / Dm);
    __syncthreads();
    float dx = v.x - mean, dy = v.y - mean;
    red[tid] = dx * dx + dy * dy;
    __syncthreads();
    for (int off = 128; off; off >>= 1) {
        if (tid < off) red[tid] += red[tid + off];
        __syncthreads();
    }
    float rstd = rsqrtf(red[0] * (1.0f / Dm) + 1e-5f);
    float2 gg = ((const float2*)g)[tid];
    float2 bb = ((const float2*)bta)[tid];
    float2 o;
    o.x = dx * rstd * gg.x + bb.x;
    o.y = dy * rstd * gg.y + bb.y;
    ((float2*)(out + (size_t)r * Dm))[tid] = o;
}

// ---------------- concat [h | y | zero-pad] ----------------
__global__ void concat_kernel(const float* __restrict__ h, const float* __restrict__ y,
                              int O, int ldc, float* __restrict__ out)
{
    int total = ROWS * ldc;
    int i = blockIdx.x * blockDim.x + threadIdx.x;
    int stride = gridDim.x * blockDim.x;
    for (; i < total; i += stride) {
        int r = i / ldc, c = i - r * ldc;
        float v;
        if (c < Dm)            v = h[(size_t)r * Dm + c];
        else if (c < Dm + O)   v = y[(size_t)r * O + (c - Dm)];
        else                   v = 0.0f;
        out[i] = v;
    }
}

// ---------------- SGEMM: C = act(A@W + bias) [+ res] ----------------
// A: M x K (lda >= K, lda%8==0, padded cols of A are zero)
// W: K x N row-major.  M multiple of 128.
#define BM 128
#define BN 128
#define BK 8

__global__ __launch_bounds__(256) void gemm_kernel(
    const float* __restrict__ A, int lda,
    const float* __restrict__ W,
    const float* __restrict__ bias,
    const float* __restrict__ res,
    float* __restrict__ C,
    int M, int N, int K, int act)
{
    __shared__ float As[BK][BM];
    __shared__ float Bs[BK][BN];
    int tid = threadIdx.x;
    int tx = tid & 15, ty = tid >> 4;
    int m0 = blockIdx.y * BM;
    int n0 = blockIdx.x * BN;

    float acc[8][8];
#pragma unroll
    for (int i = 0; i < 8; i++)
#pragma unroll
        for (int j = 0; j < 8; j++) acc[i][j] = 0.0f;

    int ktiles = (K + BK - 1) / BK;
    int arow = tid >> 1;
    int aseg = (tid & 1) * 4;
    int bk   = tid >> 5;
    int bn   = (tid & 31) * 4;
    bool nvec = ((N & 3) == 0);

    for (int kt = 0; kt < ktiles; kt++) {
        int k0 = kt * BK;
        // A tile (always in-bounds: lda padded, M multiple of 128)
        float4 av = *(const float4*)(A + (size_t)(m0 + arow) * lda + k0 + aseg);
        As[aseg + 0][arow] = av.x;
        As[aseg + 1][arow] = av.y;
        As[aseg + 2][arow] = av.z;
        As[aseg + 3][arow] = av.w;
        // B tile (guard K and N)
        int gk = k0 + bk;
        int gn = n0 + bn;
        float4 bv = make_float4(0.f, 0.f, 0.f, 0.f);
        if (gk < K) {
            const float* wrow = W + (size_t)gk * N;
            if (nvec && gn + 3 < N) {
                bv = *(const float4*)(wrow + gn);
            } else {
                if (gn + 0 < N) bv.x = wrow[gn + 0];
                if (gn + 1 < N) bv.y = wrow[gn + 1];
                if (gn + 2 < N) bv.z = wrow[gn + 2];
                if (gn + 3 < N) bv.w = wrow[gn + 3];
            }
        }
        *(float4*)&Bs[bk][bn] = bv;
        __syncthreads();

#pragma unroll
        for (int k = 0; k < BK; k++) {
            float4 a0 = *(const float4*)&As[k][ty * 8];
            float4 a1 = *(const float4*)&As[k][ty * 8 + 4];
            float4 b0 = *(const float4*)&Bs[k][tx * 8];
            float4 b1 = *(const float4*)&Bs[k][tx * 8 + 4];
            float ar[8] = {a0.x, a0.y, a0.z, a0.w, a1.x, a1.y, a1.z, a1.w};
            float br[8] = {b0.x, b0.y, b0.z, b0.w, b1.x, b1.y, b1.z, b1.w};
#pragma unroll
            for (int i = 0; i < 8; i++)
#pragma unroll
                for (int j = 0; j < 8; j++)
                    acc[i][j] += ar[i] * br[j];
        }
        __syncthreads();
    }

    // epilogue
#pragma unroll
    for (int i = 0; i < 8; i++) {
        int m = m0 + ty * 8 + i;
#pragma unroll
        for (int j = 0; j < 8; j++) {
            int n = n0 + tx * 8 + j;
            if (n < N) {
                float v = acc[i][j];
                if (bias) v += bias[n];
                if (act)  v = gelu_exact(v);
                if (res)  v += res[(size_t)m * N + n];
                C[(size_t)m * N + n] = v;
            }
        }
    }
}

// ---------------- flash attention: 64 queries per block ----------------
// qkv: [ROWS, 1536] = [q(512) | k(512) | v(512)], out: [ROWS, 512]
#define APAD 68
#define ATT_SMEM (3 * 64 * APAD * 4)

__global__ __launch_bounds__(256) void attn_kernel(
    const float* __restrict__ qkv, float* __restrict__ out)
{
    extern __shared__ float sm[];
    float* qs  = sm;                  // [d][qr] 64x68 (Q transposed)
    float* ktp = sm + 64 * APAD;      // [d][j] K^T; reused as P^T [j][qr]
    float* vt  = sm + 2 * 64 * APAD;  // [j][d]
    __shared__ float mrow[64], lrow[64];

    int tid = threadIdx.x;
    int tx = tid & 15, ty = tid >> 4;
    int q0 = blockIdx.x * 64;
    int h  = blockIdx.y;
    int b  = blockIdx.z;
    const float scale = 0.125f;  // DH^-0.5

    const float* base = qkv + (size_t)b * Tt * QKVW;

    // load Q tile transposed: qs[d][qr]
#pragma unroll
    for (int it = 0; it < 4; it++) {
        int f = tid + it * 256;       // float4 index 0..1023
        int r = f >> 4;               // query in tile
        int d = (f & 15) << 2;
        float4 v = *(const float4*)(base + (size_t)(q0 + r) * QKVW + h * DHh + d);
        qs[(d + 0) * APAD + r] = v.x;
        qs[(d + 1) * APAD + r] = v.y;
        qs[(d + 2) * APAD + r] = v.z;
        qs[(d + 3) * APAD + r] = v.w;
    }
    if (tid < 64) { mrow[tid] = -1e30f; lrow[tid] = 0.0f; }

    float o[4][4];
#pragma unroll
    for (int i = 0; i < 4; i++)
#pragma unroll
        for (int j = 0; j < 4; j++) o[i][j] = 0.0f;

    __syncthreads();

    for (int jt = 0; jt < Tt; jt += 64) {
        // load K (transposed) + V (direct)
#pragma unroll
        for (int it = 0; it < 4; it++) {
            int f = tid + it * 256;
            int r = f >> 4;
            int d = (f & 15) << 2;
            const float* kp = base + (size_t)(jt + r) * QKVW + Hh * DHh + h * DHh + d;
            float4 kv = *(const float4*)kp;
            ktp[(d + 0) * APAD + r] = kv.x;
            ktp[(d + 1) * APAD + r] = kv.y;
            ktp[(d + 2) * APAD + r] = kv.z;
            ktp[(d + 3) * APAD + r] = kv.w;
            float4 vv = *(const float4*)(kp + Hh * DHh);  // v block is +512 from k block
            *(float4*)&vt[r * APAD + d] = vv;
        }
        __syncthreads();

        // S = (Q K^T) * scale  -> s[ri][ci], rows qr=ty*4+ri, cols j=tx*4+ci
        float s[4][4];
#pragma unroll
        for (int i = 0; i < 4; i++)
#pragma unroll
            for (int j = 0; j < 4; j++) s[i][j] = 0.0f;
#pragma unroll 16
        for (int d = 0; d < 64; d++) {
            float4 a  = *(const float4*)&qs[d * APAD + ty * 4];
            float4 bb = *(const float4*)&ktp[d * APAD + tx * 4];
            float ar[4] = {a.x, a.y, a.z, a.w};
            float br[4] = {bb.x, bb.y, bb.z, bb.w};
#pragma unroll
            for (int i = 0; i < 4; i++)
#pragma unroll
                for (int j = 0; j < 4; j++)
                    s[i][j] += ar[i] * br[j];
        }

        // online softmax per row (16 threads per row, shfl width 16)
        float fscale[4];
#pragma unroll
        for (int ri = 0; ri < 4; ri++) {
            float rm = fmaxf(fmaxf(s[ri][0] * scale, s[ri][1] * scale),
                             fmaxf(s[ri][2] * scale, s[ri][3] * scale));
#pragma unroll
            for (int off = 8; off; off >>= 1)
                rm = fmaxf(rm, __shfl_xor_sync(0xffffffffu, rm, off, 16));
            int qr = ty * 4 + ri;
            float mold = mrow[qr];
            float mnew = fmaxf(mold, rm);
            fscale[ri] = __expf(mold - mnew);
            float psum = 0.0f;
#pragma unroll
            for (int ci = 0; ci < 4; ci++) {
                s[ri][ci] = __expf(s[ri][ci] * scale - mnew);
                psum += s[ri][ci];
            }
#pragma unroll
            for (int off = 8; off; off >>= 1)
                psum += __shfl_xor_sync(0xffffffffu, psum, off, 16);
            __syncwarp();
            if (tx == 0) {
                mrow[qr] = mnew;
                lrow[qr] = lrow[qr] * fscale[ri] + psum;
            }
        }
        __syncthreads();  // everyone done reading ktp as K^T

        // write P^T into ktp: pst[j][qr]
#pragma unroll
        for (int ri = 0; ri < 4; ri++)
#pragma unroll
            for (int ci = 0; ci < 4; ci++)
                ktp[(tx * 4 + ci) * APAD + ty * 4 + ri] = s[ri][ci];
        __syncthreads();

        // rescale O, then O += P V   (rows qr=ty*4+ri, cols d=tx*4+ci)
#pragma unroll
        for (int ri = 0; ri < 4; ri++)
#pragma unroll
            for (int ci = 0; ci < 4; ci++)
                o[ri][ci] *= fscale[ri];
#pragma unroll 16
        for (int j = 0; j < 64; j++) {
            float4 a  = *(const float4*)&ktp[j * APAD + ty * 4];
            float4 bb = *(const float4*)&vt[j * APAD + tx * 4];
            float ar[4] = {a.x, a.y, a.z, a.w};
            float br[4] = {bb.x, bb.y, bb.z, bb.w};
#pragma unroll
            for (int i = 0; i < 4; i++)
#pragma unroll
                for (int jj = 0; jj < 4; jj++)
                    o[i][jj] += ar[i] * br[jj];
        }
        __syncthreads();  // before next tile overwrites ktp/vt
    }

    // finalize: divide by l, write out[row, h*64 + d]
#pragma unroll
    for (int ri = 0; ri < 4; ri++) {
        int qr = ty * 4 + ri;
        float inv = 1.0f / lrow[qr];
        float4 ov = make_float4(o[ri][0] * inv, o[ri][1] * inv, o[ri][2] * inv, o[ri][3] * inv);
        *(float4*)(out + (size_t)(b * Tt + q0 + qr) * Dm + h * DHh + tx * 4) = ov;
    }
}

// ---------------- host launcher ----------------
extern "C" void kernel_launch(void* const* d_in, const int* in_sizes, int n_in,
                              void* d_out, int out_size)
{
    const float* x     = (const float*)d_in[0];
    const float* init0 = (const float*)d_in[1];
    const float* init1 = (const float*)d_in[2];
    // d_in[3] = mask : all-true by construction, ignored
    const float* ln1_g = (const float*)d_in[4];
    const float* ln1_b = (const float*)d_in[5];
    const float* qkv_W = (const float*)d_in[6];
    const float* out_W = (const float*)d_in[7];
    const float* out_b = (const float*)d_in[8];
    const float* ln2_g = (const float*)d_in[9];
    const float* ln2_b = (const float*)d_in[10];
    const float* ff_W1 = (const float*)d_in[11];
    const float* ff_b1 = (const float*)d_in[12];
    const float* ff_W2 = (const float*)d_in[13];
    const float* ff_b2 = (const float*)d_in[14];
    const float* ln3_g = (const float*)d_in[15];
    const float* ln3_b = (const float*)d_in[16];
    const float* r0_W1 = (const float*)d_in[17];
    const float* r0_b1 = (const float*)d_in[18];
    const float* r0_W2 = (const float*)d_in[19];
    const float* r0_b2 = (const float*)d_in[20];
    const float* ln4_g = (const float*)d_in[21];
    const float* ln4_b = (const float*)d_in[22];
    const float* r1_W1 = (const float*)d_in[23];
    const float* r1_b1 = (const float*)d_in[24];
    const float* r1_W2 = (const float*)d_in[25];
    const float* r1_b2 = (const float*)d_in[26];
    float* outp = (float*)d_out;

    float *gx, *gh, *gqkv, *gatt, *gff, *gcat, *gy0, *gy1;
    cudaGetSymbolAddress((void**)&gx,   g_x);
    cudaGetSymbolAddress((void**)&gh,   g_h);
    cudaGetSymbolAddress((void**)&gqkv, g_qkv);
    cudaGetSymbolAddress((void**)&gatt, g_att);
    cudaGetSymbolAddress((void**)&gff,  g_ff);
    cudaGetSymbolAddress((void**)&gcat, g_cat);
    cudaGetSymbolAddress((void**)&gy0,  g_y0);
    cudaGetSymbolAddress((void**)&gy1,  g_y1);

    cudaFuncSetAttribute(attn_kernel, cudaFuncAttributeMaxDynamicSharedMemorySize, ATT_SMEM);

    copy_kernel<<<2048, 256>>>(x,     gx,  ROWS * Dm);
    copy_kernel<<<512,  256>>>(init0, gy0, ROWS * O0);
    copy_kernel<<<48,   256>>>(init1, gy1, ROWS * O1);

    for (int l = 0; l < LAYERS; l++) {
        // --- attention block ---
        ln_kernel<<<ROWS, 256>>>(gx, ln1_g + l * Dm, ln1_b + l * Dm, gh);
        gemm_kernel<<<dim3(QKVW / BN, ROWS / BM), 256>>>(
            gh, Dm, qkv_W + (size_t)l * Dm * QKVW, nullptr, nullptr, gqkv,
            ROWS, QKVW, Dm, 0);
        attn_kernel<<<dim3(Tt / 64, Hh, Bb), 256, ATT_SMEM>>>(gqkv, gatt);
        gemm_kernel<<<dim3(Dm / BN, ROWS / BM), 256>>>(
            gatt, Dm, out_W + (size_t)l * Dm * Dm, out_b + l * Dm, gx, gx,
            ROWS, Dm, Dm, 0);
        // --- FFN block ---
        ln_kernel<<<ROWS, 256>>>(gx, ln2_g + l * Dm, ln2_b + l * Dm, gh);
        gemm_kernel<<<dim3(Mff / BN, ROWS / BM), 256>>>(
            gh, Dm, ff_W1 + (size_t)l * Dm * Mff, ff_b1 + l * Mff, nullptr, gff,
            ROWS, Mff, Dm, 1);
        gemm_kernel<<<dim3(Dm / BN, ROWS / BM), 256>>>(
            gff, Mff, ff_W2 + (size_t)l * Mff * Dm, ff_b2 + l * Dm, gx, gx,
            ROWS, Dm, Mff, 0);
        // --- regressor 0 ---
        ln_kernel<<<ROWS, 256>>>(gx, ln3_g + l * Dm, ln3_b + l * Dm, gh);
        concat_kernel<<<2048, 256>>>(gh, gy0, O0, CAT0, gcat);
        gemm_kernel<<<dim3(Mff / BN, ROWS / BM), 256>>>(
            gcat, CAT0, r0_W1 + (size_t)l * (Dm + O0) * Mff, r0_b1 + l * Mff, nullptr, gff,
            ROWS, Mff, Dm + O0, 1);
        gemm_kernel<<<dim3((O0 + BN - 1) / BN, ROWS / BM), 256>>>(
            gff, Mff, r0_W2 + (size_t)l * Mff * O0, r0_b2 + l * O0, gy0, gy0,
            ROWS, O0, Mff, 0);
        // --- regressor 1 ---
        ln_kernel<<<ROWS, 256>>>(gx, ln4_g + l * Dm, ln4_b + l * Dm, gh);
        concat_kernel<<<2048, 256>>>(gh, gy1, O1, CAT1, gcat);
        gemm_kernel<<<dim3(Mff / BN, ROWS / BM), 256>>>(
            gcat, CAT1, r1_W1 + (size_t)l * (Dm + O1) * Mff, r1_b1 + l * Mff, nullptr, gff,
            ROWS, Mff, Dm + O1, 1);
        gemm_kernel<<<dim3((O1 + BN - 1) / BN, ROWS / BM), 256>>>(
            gff, Mff, r1_W2 + (size_t)l * Mff * O1, r1_b2 + l * O1, gy1, gy1,
            ROWS, O1, Mff, 0);
    }

    // output: y0 flattened then y1 flattened
    copy_kernel<<<512, 256>>>(gy0, outp, ROWS * O0);
    copy_kernel<<<48,  256>>>(gy1, outp + ROWS * O0, ROWS * O1);
}

// round 3
// speedup vs baseline: 2.4200x; 2.4200x over previous
#include <cuda_runtime.h>
#include <cuda_bf16.h>
#include <math.h>
#include <stdint.h>

// ---------------- problem constants ----------------
#define LAYERS 2
#define Dm     512
#define Hh     8
#define DHh    64
#define Mff    2048
#define O0     132
#define O1     3
#define Bb     2
#define Tt     2048
#define ROWS   (Bb*Tt)          // 4096
#define QKVW   (3*Hh*DHh)       // 1536
#define CAT0   656              // 644 padded to mult of 16
#define CAT1   528              // 515 padded to mult of 16

// ---------------- scratch (device globals, no allocs) ----------------
__device__ __align__(128) float g_x  [ROWS * Dm];
__device__ __align__(128) float g_h  [ROWS * Dm];
__device__ __align__(128) float g_qkv[ROWS * QKVW];
__device__ __align__(128) float g_att[ROWS * Dm];
__device__ __align__(128) float g_ff [ROWS * Mff];
__device__ __align__(128) float g_cat[ROWS * CAT0];
__device__ __align__(128) float g_y0 [ROWS * O0];
__device__ __align__(128) float g_y1 [ROWS * O1];

// ---------------- helpers ----------------
__device__ __forceinline__ float gelu_exact(float x) {
    return 0.5f * x * (1.0f + erff(x * 0.70710678118654752f));
}

__device__ __forceinline__ uint32_t f2tf(float f) {
    uint32_t u;
    asm("cvt.rna.tf32.f32 %0, %1;" : "=r"(u) : "f"(f));
    return u;
}

__device__ __forceinline__ void mma_tf32(float* d, const uint32_t* a, const uint32_t* b) {
    asm volatile("mma.sync.aligned.m16n8k8.row.col.f32.tf32.tf32.f32 "
        "{%0,%1,%2,%3}, {%4,%5,%6,%7}, {%8,%9}, {%0,%1,%2,%3};\n"
        : "+f"(d[0]), "+f"(d[1]), "+f"(d[2]), "+f"(d[3])
        : "r"(a[0]), "r"(a[1]), "r"(a[2]), "r"(a[3]), "r"(b[0]), "r"(b[1]));
}

__device__ __forceinline__ void cp16(void* dst, const void* src) {
    uint32_t d = (uint32_t)__cvta_generic_to_shared(dst);
    asm volatile("cp.async.cg.shared.global [%0], [%1], 16;\n" :: "r"(d), "l"(src));
}
__device__ __forceinline__ void cp4(void* dst, const void* src, bool p) {
    uint32_t d = (uint32_t)__cvta_generic_to_shared(dst);
    int sz = p ? 4 : 0;
    asm volatile("cp.async.ca.shared.global [%0], [%1], 4, %2;\n" :: "r"(d), "l"(src), "r"(sz));
}
__device__ __forceinline__ void cp_commit() { asm volatile("cp.async.commit_group;\n"); }
template <int NN>
__device__ __forceinline__ void cp_wait() { asm volatile("cp.async.wait_group %0;\n" :: "n"(NN)); }

// ---------------- elementwise copy ----------------
__global__ void copy_kernel(const float* __restrict__ src, float* __restrict__ dst, int n) {
    int i = blockIdx.x * blockDim.x + threadIdx.x;
    int stride = gridDim.x * blockDim.x;
    for (; i < n; i += stride) dst[i] = src[i];
}

// ---------------- layernorm: warp per row ----------------
__global__ __launch_bounds__(128) void ln_kernel(
    const float* __restrict__ x, const float* __restrict__ g,
    const float* __restrict__ bta, float* __restrict__ out)
{
    int wid = threadIdx.x >> 5, lane = threadIdx.x & 31;
    int row = blockIdx.x * 4 + wid;
    const float4* xr = (const float4*)(x + (size_t)row * Dm);
    float4 v[4];
    float s = 0.0f;
#pragma unroll
    for (int i = 0; i < 4; i++) {
        v[i] = xr[lane + 32 * i];
        s += (v[i].x + v[i].y) + (v[i].z + v[i].w);
    }
#pragma unroll
    for (int o = 16; o; o >>= 1) s += __shfl_xor_sync(0xffffffffu, s, o);
    float mean = s * (1.0f / Dm);
    float var = 0.0f;
#pragma unroll
    for (int i = 0; i < 4; i++) {
        v[i].x -= mean; v[i].y -= mean; v[i].z -= mean; v[i].w -= mean;
        var += v[i].x * v[i].x + v[i].y * v[i].y + v[i].z * v[i].z + v[i].w * v[i].w;
    }
#pragma unroll
    for (int o = 16; o; o >>= 1) var += __shfl_xor_sync(0xffffffffu, var, o);
    float rstd = rsqrtf(var * (1.0f / Dm) + 1e-5f);
    const float4* gr = (const float4*)g;
    const float4* br = (const float4*)bta;
    float4* orow = (float4*)(out + (size_t)row * Dm);
#pragma unroll
    for (int i = 0; i < 4; i++) {
        float4 gg = gr[lane + 32 * i];
        float4 bb = br[lane + 32 * i];
        float4 o;
        o.x = v[i].x * rstd * gg.x + bb.x;
        o.y = v[i].y * rstd * gg.y + bb.y;
        o.z = v[i].z * rstd * gg.z + bb.z;
        o.w = v[i].w * rstd * gg.w + bb.w;
        orow[lane + 32 * i] = o;
    }
}

// ---------------- concat [h | y | zero-pad] ----------------
__global__ void concat_kernel(const float* __restrict__ h, const float* __restrict__ y,
                              int O, int ldc, float* __restrict__ out)
{
    int total = ROWS * ldc;
    int i = blockIdx.x * blockDim.x + threadIdx.x;
    int stride = gridDim.x * blockDim.x;
    for (; i < total; i += stride) {
        int r = i / ldc, c = i - r * ldc;
        float v;
        if (c < Dm)            v = h[(size_t)r * Dm + c];
        else if (c < Dm + O)   v = y[(size_t)r * O + (c - Dm)];
        else                   v = 0.0f;
        out[i] = v;
    }
}

// ---------------- tf32 tensor-core GEMM ----------------
// C[M,N] = act(A[M,Kpad] @ W[Ktrue,N] + bias) [+ res]
// A row-major with lda == Kpad (mult of 16, pad cols zero). M mult of 128.
// Block: 128x128 tile, 256 thr (8 warps, 2x4), warp 64x32, mma m16n8k8 tf32.
#define APITCH 20
#define BPITCH 136

__global__ __launch_bounds__(256) void gemm_tf32_kernel(
    const float* __restrict__ A, int lda,
    const float* __restrict__ W,
    const float* __restrict__ bias,
    const float* __restrict__ res,
    float* __restrict__ C,
    int M, int N, int Ktrue, int act)
{
    __shared__ float As[2][128][APITCH];
    __shared__ float Bs[2][16][BPITCH];

    int tid  = threadIdx.x;
    int lane = tid & 31, wid = tid >> 5;
    int g = lane >> 2, c = lane & 3;
    int wm0 = (wid >> 2) * 64;
    int wn0 = (wid & 3) * 32;
    int m0 = blockIdx.y * 128, n0 = blockIdx.x * 128;

    float acc[4][4][4];
#pragma unroll
    for (int i = 0; i < 4; i++)
#pragma unroll
        for (int j = 0; j < 4; j++)
#pragma unroll
            for (int k = 0; k < 4; k++) acc[i][j][k] = 0.0f;

    // loader indices
    int ar = tid >> 1, ak = (tid & 1) * 8;
    int br = tid >> 5, bc = (tid & 31) * 4;

    int Kpad = lda;
    int ntiles = Kpad >> 4;

#define LOAD_TILE(t, buf)                                                     \
    {                                                                         \
        int k0_ = (t) << 4;                                                   \
        const float* ap_ = A + (size_t)(m0 + ar) * lda + k0_ + ak;            \
        cp16(&As[buf][ar][ak], ap_);                                          \
        cp16(&As[buf][ar][ak + 4], ap_ + 4);                                  \
        _Pragma("unroll")                                                     \
        for (int rr_ = 0; rr_ < 2; rr_++) {                                   \
            int gk_ = k0_ + br + rr_ * 8;                                     \
            int gn_ = n0 + bc;                                                \
            const float* bp_ = W + (size_t)gk_ * N + gn_;                     \
            float* dp_ = &Bs[buf][br + rr_ * 8][bc];                          \
            if (gk_ < Ktrue && gn_ + 3 < N) {                                 \
                cp16(dp_, bp_);                                               \
            } else {                                                          \
                _Pragma("unroll")                                             \
                for (int ii_ = 0; ii_ < 4; ii_++)                             \
                    cp4(dp_ + ii_, bp_ + ii_, gk_ < Ktrue && gn_ + ii_ < N);  \
            }                                                                 \
        }                                                                     \
    }

    LOAD_TILE(0, 0);
    cp_commit();

    for (int t = 0; t < ntiles; t++) {
        if (t + 1 < ntiles) { LOAD_TILE(t + 1, (t + 1) & 1); }
        cp_commit();
        cp_wait<1>();
        __syncthreads();

        int buf = t & 1;
#pragma unroll
        for (int kk = 0; kk < 16; kk += 8) {
            uint32_t af[4][4], bf[4][2];
#pragma unroll
            for (int mt = 0; mt < 4; mt++) {
                int m = wm0 + mt * 16 + g;
                af[mt][0] = f2tf(As[buf][m][kk + c]);
                af[mt][1] = f2tf(As[buf][m + 8][kk + c]);
                af[mt][2] = f2tf(As[buf][m][kk + c + 4]);
                af[mt][3] = f2tf(As[buf][m + 8][kk + c + 4]);
            }
#pragma unroll
            for (int nt = 0; nt < 4; nt++) {
                int n = wn0 + nt * 8 + g;
                bf[nt][0] = f2tf(Bs[buf][kk + c][n]);
                bf[nt][1] = f2tf(Bs[buf][kk + c + 4][n]);
            }
#pragma unroll
            for (int mt = 0; mt < 4; mt++)
#pragma unroll
                for (int nt = 0; nt < 4; nt++)
                    mma_tf32(acc[mt][nt], af[mt], bf[nt]);
        }
        __syncthreads();
    }

    // epilogue
    bool Neven = (N & 1) == 0;
#pragma unroll
    for (int mt = 0; mt < 4; mt++) {
#pragma unroll
        for (int nt = 0; nt < 4; nt++) {
            int col = n0 + wn0 + nt * 8 + c * 2;
#pragma unroll
            for (int hh = 0; hh < 2; hh++) {
                int row = m0 + wm0 + mt * 16 + g + hh * 8;
                float v0 = acc[mt][nt][hh * 2 + 0];
                float v1 = acc[mt][nt][hh * 2 + 1];
                size_t off = (size_t)row * N + col;
                if (Neven && col + 1 < N) {
                    if (bias) { v0 += bias[col]; v1 += bias[col + 1]; }
                    if (act)  { v0 = gelu_exact(v0); v1 = gelu_exact(v1); }
                    if (res) {
                        float2 rr = *(const float2*)(res + off);
                        v0 += rr.x; v1 += rr.y;
                    }
                    *(float2*)(C + off) = make_float2(v0, v1);
                } else {
                    if (col < N) {
                        if (bias) v0 += bias[col];
                        if (act)  v0 = gelu_exact(v0);
                        if (res)  v0 += res[off];
                        C[off] = v0;
                    }
                    if (col + 1 < N) {
                        if (bias) v1 += bias[col + 1];
                        if (act)  v1 = gelu_exact(v1);
                        if (res)  v1 += res[off + 1];
                        C[off + 1] = v1;
                    }
                }
            }
        }
    }
#undef LOAD_TILE
}

// ---------------- flash attention: 64 queries per block ----------------
// qkv: [ROWS, 1536] = [q(512) | k(512) | v(512)], out: [ROWS, 512]
#define APAD 68
#define ATT_SMEM (3 * 64 * APAD * 4)

__global__ __launch_bounds__(256) void attn_kernel(
    const float* __restrict__ qkv, float* __restrict__ out)
{
    extern __shared__ float sm[];
    float* qs  = sm;                  // [d][qr] 64x68 (Q transposed)
    float* ktp = sm + 64 * APAD;      // [d][j] K^T; reused as P^T [j][qr]
    float* vt  = sm + 2 * 64 * APAD;  // [j][d]
    __shared__ float mrow[64], lrow[64];

    int tid = threadIdx.x;
    int tx = tid & 15, ty = tid >> 4;
    int q0 = blockIdx.x * 64;
    int h  = blockIdx.y;
    int b  = blockIdx.z;
    const float scale = 0.125f;  // DH^-0.5

    const float* base = qkv + (size_t)b * Tt * QKVW;

    // load Q tile transposed: qs[d][qr]
#pragma unroll
    for (int it = 0; it < 4; it++) {
        int f = tid + it * 256;
        int r = f >> 4;
        int d = (f & 15) << 2;
        float4 v = *(const float4*)(base + (size_t)(q0 + r) * QKVW + h * DHh + d);
        qs[(d + 0) * APAD + r] = v.x;
        qs[(d + 1) * APAD + r] = v.y;
        qs[(d + 2) * APAD + r] = v.z;
        qs[(d + 3) * APAD + r] = v.w;
    }
    if (tid < 64) { mrow[tid] = -1e30f; lrow[tid] = 0.0f; }

    float o[4][4];
#pragma unroll
    for (int i = 0; i < 4; i++)
#pragma unroll
        for (int j = 0; j < 4; j++) o[i][j] = 0.0f;

    __syncthreads();

    for (int jt = 0; jt < Tt; jt += 64) {
#pragma unroll
        for (int it = 0; it < 4; it++) {
            int f = tid + it * 256;
            int r = f >> 4;
            int d = (f & 15) << 2;
            const float* kp = base + (size_t)(jt + r) * QKVW + Hh * DHh + h * DHh + d;
            float4 kv = *(const float4*)kp;
            ktp[(d + 0) * APAD + r] = kv.x;
            ktp[(d + 1) * APAD + r] = kv.y;
            ktp[(d + 2) * APAD + r] = kv.z;
            ktp[(d + 3) * APAD + r] = kv.w;
            float4 vv = *(const float4*)(kp + Hh * DHh);
            *(float4*)&vt[r * APAD + d] = vv;
        }
        __syncthreads();

        float s[4][4];
#pragma unroll
        for (int i = 0; i < 4; i++)
#pragma unroll
            for (int j = 0; j < 4; j++) s[i][j] = 0.0f;
#pragma unroll 16
        for (int d = 0; d < 64; d++) {
            float4 a  = *(const float4*)&qs[d * APAD + ty * 4];
            float4 bb = *(const float4*)&ktp[d * APAD + tx * 4];
            float ar[4] = {a.x, a.y, a.z, a.w};
            float br[4] = {bb.x, bb.y, bb.z, bb.w};
#pragma unroll
            for (int i = 0; i < 4; i++)
#pragma unroll
                for (int j = 0; j < 4; j++)
                    s[i][j] += ar[i] * br[j];
        }

        float fscale[4];
#pragma unroll
        for (int ri = 0; ri < 4; ri++) {
            float rm = fmaxf(fmaxf(s[ri][0] * scale, s[ri][1] * scale),
                             fmaxf(s[ri][2] * scale, s[ri][3] * scale));
#pragma unroll
            for (int off = 8; off; off >>= 1)
                rm = fmaxf(rm, __shfl_xor_sync(0xffffffffu, rm, off, 16));
            int qr = ty * 4 + ri;
            float mold = mrow[qr];
            float mnew = fmaxf(mold, rm);
            fscale[ri] = __expf(mold - mnew);
            float psum = 0.0f;
#pragma unroll
            for (int ci = 0; ci < 4; ci++) {
                s[ri][ci] = __expf(s[ri][ci] * scale - mnew);
                psum += s[ri][ci];
            }
#pragma unroll
            for (int off = 8; off; off >>= 1)
                psum += __shfl_xor_sync(0xffffffffu, psum, off, 16);
            __syncwarp();
            if (tx == 0) {
                mrow[qr] = mnew;
                lrow[qr] = lrow[qr] * fscale[ri] + psum;
            }
        }
        __syncthreads();

#pragma unroll
        for (int ri = 0; ri < 4; ri++)
#pragma unroll
            for (int ci = 0; ci < 4; ci++)
                ktp[(tx * 4 + ci) * APAD + ty * 4 + ri] = s[ri][ci];
        __syncthreads();

#pragma unroll
        for (int ri = 0; ri < 4; ri++)
#pragma unroll
            for (int ci = 0; ci < 4; ci++)
                o[ri][ci] *= fscale[ri];
#pragma unroll 16
        for (int j = 0; j < 64; j++) {
            float4 a  = *(const float4*)&ktp[j * APAD + ty * 4];
            float4 bb = *(const float4*)&vt[j * APAD + tx * 4];
            float ar[4] = {a.x, a.y, a.z, a.w};
            float br[4] = {bb.x, bb.y, bb.z, bb.w};
#pragma unroll
            for (int i = 0; i < 4; i++)
#pragma unroll
                for (int jj = 0; jj < 4; jj++)
                    o[i][jj] += ar[i] * br[jj];
        }
        __syncthreads();
    }

#pragma unroll
    for (int ri = 0; ri < 4; ri++) {
        int qr = ty * 4 + ri;
        float inv = 1.0f / lrow[qr];
        float4 ov = make_float4(o[ri][0] * inv, o[ri][1] * inv, o[ri][2] * inv, o[ri][3] * inv);
        *(float4*)(out + (size_t)(b * Tt + q0 + qr) * Dm + h * DHh + tx * 4) = ov;
    }
}

// ---------------- host launcher ----------------
extern "C" void kernel_launch(void* const* d_in, const int* in_sizes, int n_in,
                              void* d_out, int out_size)
{
    const float* x     = (const float*)d_in[0];
    const float* init0 = (const float*)d_in[1];
    const float* init1 = (const float*)d_in[2];
    // d_in[3] = mask : all-true by construction, ignored
    const float* ln1_g = (const float*)d_in[4];
    const float* ln1_b = (const float*)d_in[5];
    const float* qkv_W = (const float*)d_in[6];
    const float* out_W = (const float*)d_in[7];
    const float* out_b = (const float*)d_in[8];
    const float* ln2_g = (const float*)d_in[9];
    const float* ln2_b = (const float*)d_in[10];
    const float* ff_W1 = (const float*)d_in[11];
    const float* ff_b1 = (const float*)d_in[12];
    const float* ff_W2 = (const float*)d_in[13];
    const float* ff_b2 = (const float*)d_in[14];
    const float* ln3_g = (const float*)d_in[15];
    const float* ln3_b = (const float*)d_in[16];
    const float* r0_W1 = (const float*)d_in[17];
    const float* r0_b1 = (const float*)d_in[18];
    const float* r0_W2 = (const float*)d_in[19];
    const float* r0_b2 = (const float*)d_in[20];
    const float* ln4_g = (const float*)d_in[21];
    const float* ln4_b = (const float*)d_in[22];
    const float* r1_W1 = (const float*)d_in[23];
    const float* r1_b1 = (const float*)d_in[24];
    const float* r1_W2 = (const float*)d_in[25];
    const float* r1_b2 = (const float*)d_in[26];
    float* outp = (float*)d_out;

    float *gx, *gh, *gqkv, *gatt, *gff, *gcat, *gy0, *gy1;
    cudaGetSymbolAddress((void**)&gx,   g_x);
    cudaGetSymbolAddress((void**)&gh,   g_h);
    cudaGetSymbolAddress((void**)&gqkv, g_qkv);
    cudaGetSymbolAddress((void**)&gatt, g_att);
    cudaGetSymbolAddress((void**)&gff,  g_ff);
    cudaGetSymbolAddress((void**)&gcat, g_cat);
    cudaGetSymbolAddress((void**)&gy0,  g_y0);
    cudaGetSymbolAddress((void**)&gy1,  g_y1);

    cudaFuncSetAttribute(attn_kernel, cudaFuncAttributeMaxDynamicSharedMemorySize, ATT_SMEM);

    copy_kernel<<<2048, 256>>>(x,     gx,  ROWS * Dm);
    copy_kernel<<<512,  256>>>(init0, gy0, ROWS * O0);
    copy_kernel<<<48,   256>>>(init1, gy1, ROWS * O1);

    for (int l = 0; l < LAYERS; l++) {
        // --- attention block ---
        ln_kernel<<<ROWS / 4, 128>>>(gx, ln1_g + l * Dm, ln1_b + l * Dm, gh);
        gemm_tf32_kernel<<<dim3(QKVW / 128, ROWS / 128), 256>>>(
            gh, Dm, qkv_W + (size_t)l * Dm * QKVW, nullptr, nullptr, gqkv,
            ROWS, QKVW, Dm, 0);
        attn_kernel<<<dim3(Tt / 64, Hh, Bb), 256, ATT_SMEM>>>(gqkv, gatt);
        gemm_tf32_kernel<<<dim3(Dm / 128, ROWS / 128), 256>>>(
            gatt, Dm, out_W + (size_t)l * Dm * Dm, out_b + l * Dm, gx, gx,
            ROWS, Dm, Dm, 0);
        // --- FFN block ---
        ln_kernel<<<ROWS / 4, 128>>>(gx, ln2_g + l * Dm, ln2_b + l * Dm, gh);
        gemm_tf32_kernel<<<dim3(Mff / 128, ROWS / 128), 256>>>(
            gh, Dm, ff_W1 + (size_t)l * Dm * Mff, ff_b1 + l * Mff, nullptr, gff,
            ROWS, Mff, Dm, 1);
        gemm_tf32_kernel<<<dim3(Dm / 128, ROWS / 128), 256>>>(
            gff, Mff, ff_W2 + (size_t)l * Mff * Dm, ff_b2 + l * Dm, gx, gx,
            ROWS, Dm, Mff, 0);
        // --- regressor 0 ---
        ln_kernel<<<ROWS / 4, 128>>>(gx, ln3_g + l * Dm, ln3_b + l * Dm, gh);
        concat_kernel<<<2048, 256>>>(gh, gy0, O0, CAT0, gcat);
        gemm_tf32_kernel<<<dim3(Mff / 128, ROWS / 128), 256>>>(
            gcat, CAT0, r0_W1 + (size_t)l * (Dm + O0) * Mff, r0_b1 + l * Mff, nullptr, gff,
            ROWS, Mff, Dm + O0, 1);
        gemm_tf32_kernel<<<dim3((O0 + 127) / 128, ROWS / 128), 256>>>(
            gff, Mff, r0_W2 + (size_t)l * Mff * O0, r0_b2 + l * O0, gy0, gy0,
            ROWS, O0, Mff, 0);
        // --- regressor 1 ---
        ln_kernel<<<ROWS / 4, 128>>>(gx, ln4_g + l * Dm, ln4_b + l * Dm, gh);
        concat_kernel<<<2048, 256>>>(gh, gy1, O1, CAT1, gcat);
        gemm_tf32_kernel<<<dim3(Mff / 128, ROWS / 128), 256>>>(
            gcat, CAT1, r1_W1 + (size_t)l * (Dm + O1) * Mff, r1_b1 + l * Mff, nullptr, gff,
            ROWS, Mff, Dm + O1, 1);
        gemm_tf32_kernel<<<dim3((O1 + 127) / 128, ROWS / 128), 256>>>(
            gff, Mff, r1_W2 + (size_t)l * Mff * O1, r1_b2 + l * O1, gy1, gy1,
            ROWS, O1, Mff, 0);
    }

    // output: y0 flattened then y1 flattened
    copy_kernel<<<512, 256>>>(gy0, outp, ROWS * O0);
    copy_kernel<<<48,  256>>>(gy1, outp + ROWS * O0, ROWS * O1);
}

// round 4
// speedup vs baseline: 3.4238x; 1.4148x over previous
#include <cuda_runtime.h>
#include <cuda_bf16.h>
#include <math.h>
#include <stdint.h>

// ---------------- problem constants ----------------
#define LAYERS 2
#define Dm     512
#define Hh     8
#define DHh    64
#define Mff    2048
#define O0     132
#define O1     3
#define Bb     2
#define Tt     2048
#define ROWS   (Bb*Tt)          // 4096
#define QKVW   (3*Hh*DHh)       // 1536
#define CAT0   656              // 644 padded to mult of 16
#define CAT1   528              // 515 padded to mult of 16

// ---------------- scratch (device globals, no allocs) ----------------
__device__ __align__(128) float g_x  [ROWS * Dm];
__device__ __align__(128) float g_h  [ROWS * Dm];
__device__ __align__(128) float g_qkv[ROWS * QKVW];
__device__ __align__(128) float g_att[ROWS * Dm];
__device__ __align__(128) float g_ff [ROWS * Mff];
__device__ __align__(128) float g_cat[ROWS * CAT0];
__device__ __align__(128) float g_y0 [ROWS * O0];
__device__ __align__(128) float g_y1 [ROWS * O1];

// ---------------- helpers ----------------
__device__ __forceinline__ float gelu_exact(float x) {
    return 0.5f * x * (1.0f + erff(x * 0.70710678118654752f));
}

__device__ __forceinline__ uint32_t f2tf(float f) {
    uint32_t u;
    asm("cvt.rna.tf32.f32 %0, %1;" : "=r"(u) : "f"(f));
    return u;
}

__device__ __forceinline__ void mma_tf32(float* d, const uint32_t* a, const uint32_t* b) {
    asm volatile("mma.sync.aligned.m16n8k8.row.col.f32.tf32.tf32.f32 "
        "{%0,%1,%2,%3}, {%4,%5,%6,%7}, {%8,%9}, {%0,%1,%2,%3};\n"
        : "+f"(d[0]), "+f"(d[1]), "+f"(d[2]), "+f"(d[3])
        : "r"(a[0]), "r"(a[1]), "r"(a[2]), "r"(a[3]), "r"(b[0]), "r"(b[1]));
}

__device__ __forceinline__ void cp16(void* dst, const void* src) {
    uint32_t d = (uint32_t)__cvta_generic_to_shared(dst);
    asm volatile("cp.async.cg.shared.global [%0], [%1], 16;\n" :: "r"(d), "l"(src));
}
__device__ __forceinline__ void cp4(void* dst, const void* src, bool p) {
    uint32_t d = (uint32_t)__cvta_generic_to_shared(dst);
    int sz = p ? 4 : 0;
    asm volatile("cp.async.ca.shared.global [%0], [%1], 4, %2;\n" :: "r"(d), "l"(src), "r"(sz));
}
__device__ __forceinline__ void cp_commit() { asm volatile("cp.async.commit_group;\n"); }
template <int NN>
__device__ __forceinline__ void cp_wait() { asm volatile("cp.async.wait_group %0;\n" :: "n"(NN)); }

// ---------------- elementwise copy ----------------
__global__ void copy_kernel(const float* __restrict__ src, float* __restrict__ dst, int n) {
    int i = blockIdx.x * blockDim.x + threadIdx.x;
    int stride = gridDim.x * blockDim.x;
    for (; i < n; i += stride) dst[i] = src[i];
}

// ---------------- layernorm: warp per row ----------------
__global__ __launch_bounds__(128) void ln_kernel(
    const float* __restrict__ x, const float* __restrict__ g,
    const float* __restrict__ bta, float* __restrict__ out)
{
    int wid = threadIdx.x >> 5, lane = threadIdx.x & 31;
    int row = blockIdx.x * 4 + wid;
    const float4* xr = (const float4*)(x + (size_t)row * Dm);
    float4 v[4];
    float s = 0.0f;
#pragma unroll
    for (int i = 0; i < 4; i++) {
        v[i] = xr[lane + 32 * i];
        s += (v[i].x + v[i].y) + (v[i].z + v[i].w);
    }
#pragma unroll
    for (int o = 16; o; o >>= 1) s += __shfl_xor_sync(0xffffffffu, s, o);
    float mean = s * (1.0f / Dm);
    float var = 0.0f;
#pragma unroll
    for (int i = 0; i < 4; i++) {
        v[i].x -= mean; v[i].y -= mean; v[i].z -= mean; v[i].w -= mean;
        var += v[i].x * v[i].x + v[i].y * v[i].y + v[i].z * v[i].z + v[i].w * v[i].w;
    }
#pragma unroll
    for (int o = 16; o; o >>= 1) var += __shfl_xor_sync(0xffffffffu, var, o);
    float rstd = rsqrtf(var * (1.0f / Dm) + 1e-5f);
    const float4* gr = (const float4*)g;
    const float4* br = (const float4*)bta;
    float4* orow = (float4*)(out + (size_t)row * Dm);
#pragma unroll
    for (int i = 0; i < 4; i++) {
        float4 gg = gr[lane + 32 * i];
        float4 bb = br[lane + 32 * i];
        float4 o;
        o.x = v[i].x * rstd * gg.x + bb.x;
        o.y = v[i].y * rstd * gg.y + bb.y;
        o.z = v[i].z * rstd * gg.z + bb.z;
        o.w = v[i].w * rstd * gg.w + bb.w;
        orow[lane + 32 * i] = o;
    }
}

// ---------------- concat [h | y | zero-pad] ----------------
__global__ void concat_kernel(const float* __restrict__ h, const float* __restrict__ y,
                              int O, int ldc, float* __restrict__ out)
{
    int total = ROWS * ldc;
    int i = blockIdx.x * blockDim.x + threadIdx.x;
    int stride = gridDim.x * blockDim.x;
    for (; i < total; i += stride) {
        int r = i / ldc, c = i - r * ldc;
        float v;
        if (c < Dm)            v = h[(size_t)r * Dm + c];
        else if (c < Dm + O)   v = y[(size_t)r * O + (c - Dm)];
        else                   v = 0.0f;
        out[i] = v;
    }
}

// ---------------- tf32 tensor-core GEMM ----------------
#define APITCH 20
#define BPITCH 136

__global__ __launch_bounds__(256) void gemm_tf32_kernel(
    const float* __restrict__ A, int lda,
    const float* __restrict__ W,
    const float* __restrict__ bias,
    const float* __restrict__ res,
    float* __restrict__ C,
    int M, int N, int Ktrue, int act)
{
    __shared__ float As[2][128][APITCH];
    __shared__ float Bs[2][16][BPITCH];

    int tid  = threadIdx.x;
    int lane = tid & 31, wid = tid >> 5;
    int g = lane >> 2, c = lane & 3;
    int wm0 = (wid >> 2) * 64;
    int wn0 = (wid & 3) * 32;
    int m0 = blockIdx.y * 128, n0 = blockIdx.x * 128;

    float acc[4][4][4];
#pragma unroll
    for (int i = 0; i < 4; i++)
#pragma unroll
        for (int j = 0; j < 4; j++)
#pragma unroll
            for (int k = 0; k < 4; k++) acc[i][j][k] = 0.0f;

    int ar = tid >> 1, ak = (tid & 1) * 8;
    int br = tid >> 5, bc = (tid & 31) * 4;

    int Kpad = lda;
    int ntiles = Kpad >> 4;

#define LOAD_TILE(t, buf)                                                     \
    {                                                                         \
        int k0_ = (t) << 4;                                                   \
        const float* ap_ = A + (size_t)(m0 + ar) * lda + k0_ + ak;            \
        cp16(&As[buf][ar][ak], ap_);                                          \
        cp16(&As[buf][ar][ak + 4], ap_ + 4);                                  \
        _Pragma("unroll")                                                     \
        for (int rr_ = 0; rr_ < 2; rr_++) {                                   \
            int gk_ = k0_ + br + rr_ * 8;                                     \
            int gn_ = n0 + bc;                                                \
            const float* bp_ = W + (size_t)gk_ * N + gn_;                     \
            float* dp_ = &Bs[buf][br + rr_ * 8][bc];                          \
            if (gk_ < Ktrue && gn_ + 3 < N) {                                 \
                cp16(dp_, bp_);                                               \
            } else {                                                          \
                _Pragma("unroll")                                             \
                for (int ii_ = 0; ii_ < 4; ii_++)                             \
                    cp4(dp_ + ii_, bp_ + ii_, gk_ < Ktrue && gn_ + ii_ < N);  \
            }                                                                 \
        }                                                                     \
    }

    LOAD_TILE(0, 0);
    cp_commit();

    for (int t = 0; t < ntiles; t++) {
        if (t + 1 < ntiles) { LOAD_TILE(t + 1, (t + 1) & 1); }
        cp_commit();
        cp_wait<1>();
        __syncthreads();

        int buf = t & 1;
#pragma unroll
        for (int kk = 0; kk < 16; kk += 8) {
            uint32_t af[4][4], bf[4][2];
#pragma unroll
            for (int mt = 0; mt < 4; mt++) {
                int m = wm0 + mt * 16 + g;
                af[mt][0] = f2tf(As[buf][m][kk + c]);
                af[mt][1] = f2tf(As[buf][m + 8][kk + c]);
                af[mt][2] = f2tf(As[buf][m][kk + c + 4]);
                af[mt][3] = f2tf(As[buf][m + 8][kk + c + 4]);
            }
#pragma unroll
            for (int nt = 0; nt < 4; nt++) {
                int n = wn0 + nt * 8 + g;
                bf[nt][0] = f2tf(Bs[buf][kk + c][n]);
                bf[nt][1] = f2tf(Bs[buf][kk + c + 4][n]);
            }
#pragma unroll
            for (int mt = 0; mt < 4; mt++)
#pragma unroll
                for (int nt = 0; nt < 4; nt++)
                    mma_tf32(acc[mt][nt], af[mt], bf[nt]);
        }
        __syncthreads();
    }

    bool Neven = (N & 1) == 0;
#pragma unroll
    for (int mt = 0; mt < 4; mt++) {
#pragma unroll
        for (int nt = 0; nt < 4; nt++) {
            int col = n0 + wn0 + nt * 8 + c * 2;
#pragma unroll
            for (int hh = 0; hh < 2; hh++) {
                int row = m0 + wm0 + mt * 16 + g + hh * 8;
                float v0 = acc[mt][nt][hh * 2 + 0];
                float v1 = acc[mt][nt][hh * 2 + 1];
                size_t off = (size_t)row * N + col;
                if (Neven && col + 1 < N) {
                    if (bias) { v0 += bias[col]; v1 += bias[col + 1]; }
                    if (act)  { v0 = gelu_exact(v0); v1 = gelu_exact(v1); }
                    if (res) {
                        float2 rr = *(const float2*)(res + off);
                        v0 += rr.x; v1 += rr.y;
                    }
                    *(float2*)(C + off) = make_float2(v0, v1);
                } else {
                    if (col < N) {
                        if (bias) v0 += bias[col];
                        if (act)  v0 = gelu_exact(v0);
                        if (res)  v0 += res[off];
                        C[off] = v0;
                    }
                    if (col + 1 < N) {
                        if (bias) v1 += bias[col + 1];
                        if (act)  v1 = gelu_exact(v1);
                        if (res)  v1 += res[off + 1];
                        C[off + 1] = v1;
                    }
                }
            }
        }
    }
#undef LOAD_TILE
}

// ---------------- tensor-core flash attention ----------------
// Block: 64 queries, 128 threads (4 warps, 16 q-rows each). Key tiles of 64.
// qkv: [ROWS, 1536] = [q(512) | k(512) | v(512)], out: [ROWS, 512]
#define KPITCH 68
#define VPITCH 72
#define ATT_U32 (64 * KPITCH * 2 + 64 * VPITCH + 4 * 16 * KPITCH)
#define ATT_SMEM (ATT_U32 * 4)

__global__ __launch_bounds__(128) void attn_kernel(
    const float* __restrict__ qkv, float* __restrict__ out)
{
    extern __shared__ uint32_t smu[];
    uint32_t* Qs = smu;                        // [64][KPITCH] tf32, pre-scaled
    uint32_t* Ks = Qs + 64 * KPITCH;           // [64][KPITCH] tf32
    uint32_t* Vs = Ks + 64 * KPITCH;           // [64][VPITCH] tf32
    uint32_t* Ps = Vs + 64 * VPITCH;           // per-warp [16][KPITCH] tf32

    int tid  = threadIdx.x;
    int lane = tid & 31, w = tid >> 5;
    int g = lane >> 2, c = lane & 3;
    int q0 = blockIdx.x * 64;
    int h  = blockIdx.y;
    int b  = blockIdx.z;

    const float* base = qkv + (size_t)b * Tt * QKVW;
    uint32_t* Pw = Ps + w * 16 * KPITCH;

    // load Q tile, fold in softmax scale, convert to tf32
#pragma unroll
    for (int it = 0; it < 8; it++) {
        int f = tid + it * 128;        // 0..1023 float4s
        int r = f >> 4;
        int d = (f & 15) << 2;
        float4 v = *(const float4*)(base + (size_t)(q0 + r) * QKVW + h * DHh + d);
        uint4 u;
        u.x = f2tf(v.x * 0.125f);
        u.y = f2tf(v.y * 0.125f);
        u.z = f2tf(v.z * 0.125f);
        u.w = f2tf(v.w * 0.125f);
        *(uint4*)&Qs[r * KPITCH + d] = u;
    }

    float oacc[8][4];
#pragma unroll
    for (int i = 0; i < 8; i++)
#pragma unroll
        for (int j = 0; j < 4; j++) oacc[i][j] = 0.0f;
    float m0 = -1e30f, m8 = -1e30f, l0 = 0.0f, l8 = 0.0f;

    int qr = w * 16 + g;   // row within tile (and qr+8)

    for (int jt = 0; jt < Tt; jt += 64) {
        __syncthreads();   // previous iter's consumers done (also covers Qs first use)
#pragma unroll
        for (int it = 0; it < 8; it++) {
            int f = tid + it * 128;
            int r = f >> 4;
            int d = (f & 15) << 2;
            const float* kp = base + (size_t)(jt + r) * QKVW + Hh * DHh + h * DHh + d;
            float4 kv = *(const float4*)kp;
            uint4 ku;
            ku.x = f2tf(kv.x); ku.y = f2tf(kv.y); ku.z = f2tf(kv.z); ku.w = f2tf(kv.w);
            *(uint4*)&Ks[r * KPITCH + d] = ku;
            float4 vv = *(const float4*)(kp + Hh * DHh);
            uint4 vu;
            vu.x = f2tf(vv.x); vu.y = f2tf(vv.y); vu.z = f2tf(vv.z); vu.w = f2tf(vv.w);
            *(uint4*)&Vs[r * VPITCH + d] = vu;
        }
        __syncthreads();

        // S = Q K^T (scale folded into Q)
        float sacc[8][4];
#pragma unroll
        for (int i = 0; i < 8; i++)
#pragma unroll
            for (int j = 0; j < 4; j++) sacc[i][j] = 0.0f;
#pragma unroll
        for (int kt = 0; kt < 8; kt++) {
            int ka = kt * 8 + c;
            uint32_t a[4];
            a[0] = Qs[qr * KPITCH + ka];
            a[1] = Qs[(qr + 8) * KPITCH + ka];
            a[2] = Qs[qr * KPITCH + ka + 4];
            a[3] = Qs[(qr + 8) * KPITCH + ka + 4];
#pragma unroll
            for (int nt = 0; nt < 8; nt++) {
                uint32_t bf[2];
                bf[0] = Ks[(nt * 8 + g) * KPITCH + ka];
                bf[1] = Ks[(nt * 8 + g) * KPITCH + ka + 4];
                mma_tf32(sacc[nt], a, bf);
            }
        }

        // online softmax (rows qr and qr+8 live in this lane's quad)
        float rm0 = -1e30f, rm8 = -1e30f;
#pragma unroll
        for (int nt = 0; nt < 8; nt++) {
            rm0 = fmaxf(rm0, fmaxf(sacc[nt][0], sacc[nt][1]));
            rm8 = fmaxf(rm8, fmaxf(sacc[nt][2], sacc[nt][3]));
        }
#pragma unroll
        for (int o = 1; o <= 2; o <<= 1) {
            rm0 = fmaxf(rm0, __shfl_xor_sync(0xffffffffu, rm0, o));
            rm8 = fmaxf(rm8, __shfl_xor_sync(0xffffffffu, rm8, o));
        }
        float mn0 = fmaxf(m0, rm0), mn8 = fmaxf(m8, rm8);
        float fs0 = __expf(m0 - mn0), fs8 = __expf(m8 - mn8);
        float rs0 = 0.0f, rs8 = 0.0f;
#pragma unroll
        for (int nt = 0; nt < 8; nt++) {
            float p00 = __expf(sacc[nt][0] - mn0);
            float p01 = __expf(sacc[nt][1] - mn0);
            float p10 = __expf(sacc[nt][2] - mn8);
            float p11 = __expf(sacc[nt][3] - mn8);
            rs0 += p00 + p01;
            rs8 += p10 + p11;
            uint2 u0 = make_uint2(f2tf(p00), f2tf(p01));
            uint2 u1 = make_uint2(f2tf(p10), f2tf(p11));
            *(uint2*)&Pw[g * KPITCH + nt * 8 + 2 * c] = u0;
            *(uint2*)&Pw[(g + 8) * KPITCH + nt * 8 + 2 * c] = u1;
        }
#pragma unroll
        for (int o = 1; o <= 2; o <<= 1) {
            rs0 += __shfl_xor_sync(0xffffffffu, rs0, o);
            rs8 += __shfl_xor_sync(0xffffffffu, rs8, o);
        }
        m0 = mn0; m8 = mn8;
        l0 = l0 * fs0 + rs0;
        l8 = l8 * fs8 + rs8;
#pragma unroll
        for (int nt = 0; nt < 8; nt++) {
            oacc[nt][0] *= fs0; oacc[nt][1] *= fs0;
            oacc[nt][2] *= fs8; oacc[nt][3] *= fs8;
        }
        __syncwarp();

        // O += P V
#pragma unroll
        for (int kt = 0; kt < 8; kt++) {
            int ka = kt * 8 + c;
            uint32_t a[4];
            a[0] = Pw[g * KPITCH + ka];
            a[1] = Pw[(g + 8) * KPITCH + ka];
            a[2] = Pw[g * KPITCH + ka + 4];
            a[3] = Pw[(g + 8) * KPITCH + ka + 4];
#pragma unroll
            for (int nt = 0; nt < 8; nt++) {
                uint32_t bf[2];
                bf[0] = Vs[(kt * 8 + c) * VPITCH + nt * 8 + g];
                bf[1] = Vs[(kt * 8 + c + 4) * VPITCH + nt * 8 + g];
                mma_tf32(oacc[nt], a, bf);
            }
        }
    }

    // finalize
    float inv0 = 1.0f / l0, inv8 = 1.0f / l8;
    size_t row0 = (size_t)(b * Tt + q0 + qr);
#pragma unroll
    for (int nt = 0; nt < 8; nt++) {
        int col = h * DHh + nt * 8 + 2 * c;
        *(float2*)(out + row0 * Dm + col) =
            make_float2(oacc[nt][0] * inv0, oacc[nt][1] * inv0);
        *(float2*)(out + (row0 + 8) * Dm + col) =
            make_float2(oacc[nt][2] * inv8, oacc[nt][3] * inv8);
    }
}

// ---------------- host launcher ----------------
extern "C" void kernel_launch(void* const* d_in, const int* in_sizes, int n_in,
                              void* d_out, int out_size)
{
    const float* x     = (const float*)d_in[0];
    const float* init0 = (const float*)d_in[1];
    const float* init1 = (const float*)d_in[2];
    // d_in[3] = mask : all-true by construction, ignored
    const float* ln1_g = (const float*)d_in[4];
    const float* ln1_b = (const float*)d_in[5];
    const float* qkv_W = (const float*)d_in[6];
    const float* out_W = (const float*)d_in[7];
    const float* out_b = (const float*)d_in[8];
    const float* ln2_g = (const float*)d_in[9];
    const float* ln2_b = (const float*)d_in[10];
    const float* ff_W1 = (const float*)d_in[11];
    const float* ff_b1 = (const float*)d_in[12];
    const float* ff_W2 = (const float*)d_in[13];
    const float* ff_b2 = (const float*)d_in[14];
    const float* ln3_g = (const float*)d_in[15];
    const float* ln3_b = (const float*)d_in[16];
    const float* r0_W1 = (const float*)d_in[17];
    const float* r0_b1 = (const float*)d_in[18];
    const float* r0_W2 = (const float*)d_in[19];
    const float* r0_b2 = (const float*)d_in[20];
    const float* ln4_g = (const float*)d_in[21];
    const float* ln4_b = (const float*)d_in[22];
    const float* r1_W1 = (const float*)d_in[23];
    const float* r1_b1 = (const float*)d_in[24];
    const float* r1_W2 = (const float*)d_in[25];
    const float* r1_b2 = (const float*)d_in[26];
    float* outp = (float*)d_out;

    float *gx, *gh, *gqkv, *gatt, *gff, *gcat, *gy0, *gy1;
    cudaGetSymbolAddress((void**)&gx,   g_x);
    cudaGetSymbolAddress((void**)&gh,   g_h);
    cudaGetSymbolAddress((void**)&gqkv, g_qkv);
    cudaGetSymbolAddress((void**)&gatt, g_att);
    cudaGetSymbolAddress((void**)&gff,  g_ff);
    cudaGetSymbolAddress((void**)&gcat, g_cat);
    cudaGetSymbolAddress((void**)&gy0,  g_y0);
    cudaGetSymbolAddress((void**)&gy1,  g_y1);

    cudaFuncSetAttribute(attn_kernel, cudaFuncAttributeMaxDynamicSharedMemorySize, ATT_SMEM);

    copy_kernel<<<2048, 256>>>(x,     gx,  ROWS * Dm);
    copy_kernel<<<512,  256>>>(init0, gy0, ROWS * O0);
    copy_kernel<<<48,   256>>>(init1, gy1, ROWS * O1);

    for (int l = 0; l < LAYERS; l++) {
        // --- attention block ---
        ln_kernel<<<ROWS / 4, 128>>>(gx, ln1_g + l * Dm, ln1_b + l * Dm, gh);
        gemm_tf32_kernel<<<dim3(QKVW / 128, ROWS / 128), 256>>>(
            gh, Dm, qkv_W + (size_t)l * Dm * QKVW, nullptr, nullptr, gqkv,
            ROWS, QKVW, Dm, 0);
        attn_kernel<<<dim3(Tt / 64, Hh, Bb), 128, ATT_SMEM>>>(gqkv, gatt);
        gemm_tf32_kernel<<<dim3(Dm / 128, ROWS / 128), 256>>>(
            gatt, Dm, out_W + (size_t)l * Dm * Dm, out_b + l * Dm, gx, gx,
            ROWS, Dm, Dm, 0);
        // --- FFN block ---
        ln_kernel<<<ROWS / 4, 128>>>(gx, ln2_g + l * Dm, ln2_b + l * Dm, gh);
        gemm_tf32_kernel<<<dim3(Mff / 128, ROWS / 128), 256>>>(
            gh, Dm, ff_W1 + (size_t)l * Dm * Mff, ff_b1 + l * Mff, nullptr, gff,
            ROWS, Mff, Dm, 1);
        gemm_tf32_kernel<<<dim3(Dm / 128, ROWS / 128), 256>>>(
            gff, Mff, ff_W2 + (size_t)l * Mff * Dm, ff_b2 + l * Dm, gx, gx,
            ROWS, Dm, Mff, 0);
        // --- regressor 0 ---
        ln_kernel<<<ROWS / 4, 128>>>(gx, ln3_g + l * Dm, ln3_b + l * Dm, gh);
        concat_kernel<<<2048, 256>>>(gh, gy0, O0, CAT0, gcat);
        gemm_tf32_kernel<<<dim3(Mff / 128, ROWS / 128), 256>>>(
            gcat, CAT0, r0_W1 + (size_t)l * (Dm + O0) * Mff, r0_b1 + l * Mff, nullptr, gff,
            ROWS, Mff, Dm + O0, 1);
        gemm_tf32_kernel<<<dim3((O0 + 127) / 128, ROWS / 128), 256>>>(
            gff, Mff, r0_W2 + (size_t)l * Mff * O0, r0_b2 + l * O0, gy0, gy0,
            ROWS, O0, Mff, 0);
        // --- regressor 1 ---
        ln_kernel<<<ROWS / 4, 128>>>(gx, ln4_g + l * Dm, ln4_b + l * Dm, gh);
        concat_kernel<<<2048, 256>>>(gh, gy1, O1, CAT1, gcat);
        gemm_tf32_kernel<<<dim3(Mff / 128, ROWS / 128), 256>>>(
            gcat, CAT1, r1_W1 + (size_t)l * (Dm + O1) * Mff, r1_b1 + l * Mff, nullptr, gff,
            ROWS, Mff, Dm + O1, 1);
        gemm_tf32_kernel<<<dim3((O1 + 127) / 128, ROWS / 128), 256>>>(
            gff, Mff, r1_W2 + (size_t)l * Mff * O1, r1_b2 + l * O1, gy1, gy1,
            ROWS, O1, Mff, 0);
    }

    copy_kernel<<<512, 256>>>(gy0, outp, ROWS * O0);
    copy_kernel<<<48,  256>>>(gy1, outp + ROWS * O0, ROWS * O1);
}

// round 6
// speedup vs baseline: 5.5806x; 1.6299x over previous
#include <cuda_runtime.h>
#include <cuda_bf16.h>
#include <math.h>
#include <stdint.h>

// ---------------- problem constants ----------------
#define LAYERS 2
#define Dm     512
#define Hh     8
#define DHh    64
#define Mff    2048
#define O0     132
#define O1     3
#define Bb     2
#define Tt     2048
#define ROWS   (Bb*Tt)          // 4096
#define QKVW   (3*Hh*DHh)       // 1536
#define CAT0   656              // 644 padded to mult of 16
#define CAT1   528              // 515 padded to mult of 16
#define WPTOT  5847040          // packed-weight u32 count (both layers)

// ---------------- scratch (device globals, no allocs) ----------------
__device__ __align__(128) float          g_x  [ROWS * Dm];
__device__ __align__(128) __nv_bfloat16  g_h  [ROWS * Dm];
__device__ __align__(128) __nv_bfloat16  g_qkv[ROWS * QKVW];
__device__ __align__(128) __nv_bfloat16  g_att[ROWS * Dm];
__device__ __align__(128) __nv_bfloat16  g_ff [ROWS * Mff];
__device__ __align__(128) __nv_bfloat16  g_cat[ROWS * CAT0];
__device__ __align__(128) float          g_y0 [ROWS * O0];
__device__ __align__(128) float          g_y1 [ROWS * O1];
__device__ __align__(128) uint32_t       g_wp [WPTOT];

// ---------------- helpers ----------------
__device__ __forceinline__ float gelu_exact(float x) {
    return 0.5f * x * (1.0f + erff(x * 0.70710678118654752f));
}
__device__ __forceinline__ uint32_t pkbf(float lo, float hi) {
    uint32_t r;
    asm("cvt.rn.bf16x2.f32 %0, %1, %2;" : "=r"(r) : "f"(hi), "f"(lo));
    return r;
}
__device__ __forceinline__ float ex2f(float x) {
    float r;
    asm("ex2.approx.f32 %0, %1;" : "=f"(r) : "f"(x));
    return r;
}
__device__ __forceinline__ void mma_bf16(float* d, const uint32_t* a, const uint32_t* b) {
    asm volatile("mma.sync.aligned.m16n8k16.row.col.f32.bf16.bf16.f32 "
        "{%0,%1,%2,%3}, {%4,%5,%6,%7}, {%8,%9}, {%0,%1,%2,%3};\n"
        : "+f"(d[0]), "+f"(d[1]), "+f"(d[2]), "+f"(d[3])
        : "r"(a[0]), "r"(a[1]), "r"(a[2]), "r"(a[3]), "r"(b[0]), "r"(b[1]));
}
__device__ __forceinline__ void cp16(void* dst, const void* src) {
    uint32_t d = (uint32_t)__cvta_generic_to_shared(dst);
    asm volatile("cp.async.cg.shared.global [%0], [%1], 16;\n" :: "r"(d), "l"(src));
}
__device__ __forceinline__ void cp4(void* dst, const void* src, bool p) {
    uint32_t d = (uint32_t)__cvta_generic_to_shared(dst);
    int sz = p ? 4 : 0;
    asm volatile("cp.async.ca.shared.global [%0], [%1], 4, %2;\n" :: "r"(d), "l"(src), "r"(sz));
}
__device__ __forceinline__ void cp_commit() { asm volatile("cp.async.commit_group;\n"); }
template <int NN>
__device__ __forceinline__ void cp_wait() { asm volatile("cp.async.wait_group %0;\n" :: "n"(NN)); }

// ---------------- weight pre-pack: fp32 [K][N] -> u32 pairs [Kp2][N] ----------------
struct PackTab {
    const float* src[16];
    int off[17];
    int Ktrue[16];
    int N[16];
};

__global__ void pack_kernel(PackTab t, int total) {
    int stride = gridDim.x * blockDim.x;
    for (int i = blockIdx.x * blockDim.x + threadIdx.x; i < total; i += stride) {
        int e = 0;
        while (e < 15 && i >= t.off[e + 1]) e++;
        int loc = i - t.off[e];
        int N = t.N[e];
        int k2 = loc / N, n = loc - k2 * N;
        const float* s = t.src[e];
        int K = t.Ktrue[e];
        float lo = (2 * k2     < K) ? s[(size_t)(2 * k2)     * N + n] : 0.0f;
        float hi = (2 * k2 + 1 < K) ? s[(size_t)(2 * k2 + 1) * N + n] : 0.0f;
        g_wp[i] = pkbf(lo, hi);
    }
}

// ---------------- layernorm: warp per row, bf16 out with pitch ----------------
__global__ __launch_bounds__(128) void ln_kernel(
    const float* __restrict__ x, const float* __restrict__ g,
    const float* __restrict__ bta, __nv_bfloat16* __restrict__ out, int ldo)
{
    int wid = threadIdx.x >> 5, lane = threadIdx.x & 31;
    int row = blockIdx.x * 4 + wid;
    const float4* xr = (const float4*)(x + (size_t)row * Dm);
    float4 v[4];
    float s = 0.0f;
#pragma unroll
    for (int i = 0; i < 4; i++) {
        v[i] = xr[lane + 32 * i];
        s += (v[i].x + v[i].y) + (v[i].z + v[i].w);
    }
#pragma unroll
    for (int o = 16; o; o >>= 1) s += __shfl_xor_sync(0xffffffffu, s, o);
    float mean = s * (1.0f / Dm);
    float var = 0.0f;
#pragma unroll
    for (int i = 0; i < 4; i++) {
        v[i].x -= mean; v[i].y -= mean; v[i].z -= mean; v[i].w -= mean;
        var += v[i].x * v[i].x + v[i].y * v[i].y + v[i].z * v[i].z + v[i].w * v[i].w;
    }
#pragma unroll
    for (int o = 16; o; o >>= 1) var += __shfl_xor_sync(0xffffffffu, var, o);
    float rstd = rsqrtf(var * (1.0f / Dm) + 1e-5f);
    const float4* gr = (const float4*)g;
    const float4* br = (const float4*)bta;
    uint32_t* orow = (uint32_t*)(out + (size_t)row * ldo);
#pragma unroll
    for (int i = 0; i < 4; i++) {
        float4 gg = gr[lane + 32 * i];
        float4 bb = br[lane + 32 * i];
        uint2 u;
        u.x = pkbf(v[i].x * rstd * gg.x + bb.x, v[i].y * rstd * gg.y + bb.y);
        u.y = pkbf(v[i].z * rstd * gg.z + bb.z, v[i].w * rstd * gg.w + bb.w);
        *(uint2*)(orow + (lane + 32 * i) * 2) = u;
    }
}

// ---------------- fill y columns + zero pad of concat buffer ----------------
__global__ void caty_kernel(const float* __restrict__ y, int O, int ldc,
                            __nv_bfloat16* __restrict__ out, int total)
{
    int width = ldc - Dm;
    int stride = gridDim.x * blockDim.x;
    for (int i = blockIdx.x * blockDim.x + threadIdx.x; i < total; i += stride) {
        int r = i / width, cc = i - r * width;
        float v = (cc < O) ? y[(size_t)r * O + cc] : 0.0f;
        out[(size_t)r * ldc + Dm + cc] = __float2bfloat16(v);
    }
}

// ---------------- bf16 tensor-core GEMM ----------------
// C = act(A[M,lda]bf16 @ Wp + bias) [+res];  Wp = pair-packed bf16 [lda/2][N]
// Block 128x128, 256 thr (8 warps 2x4), warp 64x32, mma m16n8k16.
__global__ __launch_bounds__(256) void gemm_bf16_kernel(
    const __nv_bfloat16* __restrict__ A, int lda,
    const uint32_t* __restrict__ Wp,
    const float* __restrict__ bias,
    const float* __restrict__ res,
    float* __restrict__ Cf,
    __nv_bfloat16* __restrict__ Cb,
    int M, int N, int act)
{
    __shared__ uint32_t As[2][128][20];   // 128 x 16 bf16, pitch 20 words
    __shared__ uint32_t Bs[2][8][136];    // 8 k-pair rows x 128 n, pitch 136

    int tid  = threadIdx.x;
    int lane = tid & 31, wid = tid >> 5;
    int g = lane >> 2, c = lane & 3;
    int wm0 = (wid >> 2) * 64;
    int wn0 = (wid & 3) * 32;
    int m0 = blockIdx.y * 128, n0 = blockIdx.x * 128;

    float acc[4][4][4];
#pragma unroll
    for (int i = 0; i < 4; i++)
#pragma unroll
        for (int j = 0; j < 4; j++)
#pragma unroll
            for (int k = 0; k < 4; k++) acc[i][j][k] = 0.0f;

    int ar = tid >> 1, ak = (tid & 1) * 8;   // bf16 col offset in tile
    int br = tid >> 5, bc = (tid & 31) * 4;
    int ntiles = lda >> 4;

#define LOAD_TILE(t, buf)                                                     \
    {                                                                         \
        const __nv_bfloat16* ap_ = A + (size_t)(m0 + ar) * lda + (t) * 16 + ak;\
        cp16(&As[buf][ar][ak >> 1], ap_);                                     \
        int prow_ = (t) * 8 + br;                                             \
        int gn_ = n0 + bc;                                                    \
        const uint32_t* bp_ = Wp + (size_t)prow_ * N + gn_;                   \
        if (gn_ + 3 < N) {                                                    \
            cp16(&Bs[buf][br][bc], bp_);                                      \
        } else {                                                              \
            _Pragma("unroll")                                                 \
            for (int ii_ = 0; ii_ < 4; ii_++)                                 \
                cp4(&Bs[buf][br][bc + ii_], bp_ + ii_, gn_ + ii_ < N);        \
        }                                                                     \
    }

    LOAD_TILE(0, 0);
    cp_commit();

    for (int t = 0; t < ntiles; t++) {
        if (t + 1 < ntiles) { LOAD_TILE(t + 1, (t + 1) & 1); }
        cp_commit();
        cp_wait<1>();
        __syncthreads();

        int buf = t & 1;
        uint32_t af[4][4], bfr[4][2];
#pragma unroll
        for (int mt = 0; mt < 4; mt++) {
            int m = wm0 + mt * 16 + g;
            af[mt][0] = As[buf][m][c];
            af[mt][1] = As[buf][m + 8][c];
            af[mt][2] = As[buf][m][c + 4];
            af[mt][3] = As[buf][m + 8][c + 4];
        }
#pragma unroll
        for (int nt = 0; nt < 4; nt++) {
            int n = wn0 + nt * 8 + g;
            bfr[nt][0] = Bs[buf][c][n];
            bfr[nt][1] = Bs[buf][c + 4][n];
        }
#pragma unroll
        for (int mt = 0; mt < 4; mt++)
#pragma unroll
            for (int nt = 0; nt < 4; nt++)
                mma_bf16(acc[mt][nt], af[mt], bfr[nt]);
        __syncthreads();
    }

    // epilogue (vector path only for even N: odd N (e.g. N=3) makes
    // row*N odd -> float2/bf16x2 accesses misaligned)
    bool Neven = (N & 1) == 0;
#pragma unroll
    for (int mt = 0; mt < 4; mt++) {
#pragma unroll
        for (int nt = 0; nt < 4; nt++) {
            int col = n0 + wn0 + nt * 8 + c * 2;
#pragma unroll
            for (int hh = 0; hh < 2; hh++) {
                int row = m0 + wm0 + mt * 16 + g + hh * 8;
                float v0 = acc[mt][nt][hh * 2 + 0];
                float v1 = acc[mt][nt][hh * 2 + 1];
                size_t off = (size_t)row * N + col;
                if (Neven && col + 1 < N) {
                    if (bias) { v0 += bias[col]; v1 += bias[col + 1]; }
                    if (act)  { v0 = gelu_exact(v0); v1 = gelu_exact(v1); }
                    if (res) {
                        float2 rr = *(const float2*)(res + off);
                        v0 += rr.x; v1 += rr.y;
                    }
                    if (Cb) *(uint32_t*)(Cb + off) = pkbf(v0, v1);
                    else    *(float2*)(Cf + off) = make_float2(v0, v1);
                } else {
                    if (col < N) {
                        if (bias) v0 += bias[col];
                        if (act)  v0 = gelu_exact(v0);
                        if (res)  v0 += res[off];
                        if (Cb) Cb[off] = __float2bfloat16(v0);
                        else    Cf[off] = v0;
                    }
                    if (col + 1 < N) {
                        if (bias) v1 += bias[col + 1];
                        if (act)  v1 = gelu_exact(v1);
                        if (res)  v1 += res[off + 1];
                        if (Cb) Cb[off + 1] = __float2bfloat16(v1);
                        else    Cf[off + 1] = v1;
                    }
                }
            }
        }
    }
#undef LOAD_TILE
}

// ---------------- bf16 tensor-core flash attention ----------------
// Block: 64 queries, 128 threads (4 warps). qkv bf16 [ROWS,1536], out bf16 [ROWS,512]
__global__ __launch_bounds__(128) void attn_kernel(
    const __nv_bfloat16* __restrict__ qkv, __nv_bfloat16* __restrict__ out)
{
    __shared__ uint32_t Qs[64 * 20];   // 64 x 64 bf16, pitch 20 words
    __shared__ uint32_t Ks[64 * 20];
    __shared__ uint32_t Vs[32 * 72];   // 32 j-pair rows x 64 d, pitch 72

    int tid  = threadIdx.x;
    int lane = tid & 31, w = tid >> 5;
    int g = lane >> 2, c = lane & 3;
    int q0 = blockIdx.x * 64;
    int h  = blockIdx.y;
    int b  = blockIdx.z;

    const __nv_bfloat16* base = qkv + (size_t)b * Tt * QKVW;
    const float qscale = 0.125f * 1.4426950408889634f;  // DH^-.5 * log2(e)

    // load Q tile, fold scale, keep bf16
#pragma unroll
    for (int it = 0; it < 4; it++) {
        int f = tid + it * 128;       // 512 uint4 chunks
        int r = f >> 3;
        int seg = f & 7;
        uint4 q = *(const uint4*)(base + (size_t)(q0 + r) * QKVW + h * DHh + seg * 8);
        uint32_t* qw = &q.x;
        uint32_t o[4];
#pragma unroll
        for (int t = 0; t < 4; t++) {
            float lo = __uint_as_float(qw[t] << 16) * qscale;
            float hi = __uint_as_float(qw[t] & 0xFFFF0000u) * qscale;
            o[t] = pkbf(lo, hi);
        }
        *(uint4*)&Qs[r * 20 + seg * 4] = make_uint4(o[0], o[1], o[2], o[3]);
    }

    float oacc[8][4];
#pragma unroll
    for (int i = 0; i < 8; i++)
#pragma unroll
        for (int j = 0; j < 4; j++) oacc[i][j] = 0.0f;
    float m0 = -1e30f, m8 = -1e30f, l0 = 0.0f, l8 = 0.0f;
    int qr = w * 16 + g;

    for (int jt = 0; jt < Tt; jt += 64) {
        __syncthreads();
        // K: straight copy
#pragma unroll
        for (int it = 0; it < 4; it++) {
            int f = tid + it * 128;
            int r = f >> 3;
            int seg = f & 7;
            *(uint4*)&Ks[r * 20 + seg * 4] =
                *(const uint4*)(base + (size_t)(jt + r) * QKVW + Hh * DHh + h * DHh + seg * 8);
        }
        // V: pair-interleave rows 2j2/2j2+1
#pragma unroll
        for (int it = 0; it < 2; it++) {
            int f = tid + it * 128;
            int j2 = f >> 3;
            int dc = f & 7;
            const uint32_t* pa = (const uint32_t*)(base + (size_t)(jt + 2 * j2) * QKVW
                                                   + 2 * Hh * DHh + h * DHh + dc * 8);
            const uint32_t* pb = pa + (QKVW / 2);
            uint4 va = *(const uint4*)pa;
            uint4 vb = *(const uint4*)pb;
            const uint32_t* au = &va.x;
            const uint32_t* bu = &vb.x;
            uint32_t o[8];
#pragma unroll
            for (int t = 0; t < 4; t++) {
                o[2 * t + 0] = (au[t] & 0x0000FFFFu) | (bu[t] << 16);
                o[2 * t + 1] = (au[t] >> 16) | (bu[t] & 0xFFFF0000u);
            }
            uint32_t* dst = &Vs[j2 * 72 + dc * 8];
            *(uint4*)dst       = make_uint4(o[0], o[1], o[2], o[3]);
            *(uint4*)(dst + 4) = make_uint4(o[4], o[5], o[6], o[7]);
        }
        __syncthreads();

        // S = Q K^T (log2-scaled)
        float sacc[8][4];
#pragma unroll
        for (int i = 0; i < 8; i++)
#pragma unroll
            for (int j = 0; j < 4; j++) sacc[i][j] = 0.0f;
#pragma unroll
        for (int kt = 0; kt < 4; kt++) {
            uint32_t a[4];
            a[0] = Qs[qr * 20 + 8 * kt + c];
            a[1] = Qs[(qr + 8) * 20 + 8 * kt + c];
            a[2] = Qs[qr * 20 + 8 * kt + c + 4];
            a[3] = Qs[(qr + 8) * 20 + 8 * kt + c + 4];
#pragma unroll
            for (int nt = 0; nt < 8; nt++) {
                uint32_t bf[2];
                bf[0] = Ks[(nt * 8 + g) * 20 + 8 * kt + c];
                bf[1] = Ks[(nt * 8 + g) * 20 + 8 * kt + c + 4];
                mma_bf16(sacc[nt], a, bf);
            }
        }

        // online softmax in base-2
        float rm0 = -1e30f, rm8 = -1e30f;
#pragma unroll
        for (int nt = 0; nt < 8; nt++) {
            rm0 = fmaxf(rm0, fmaxf(sacc[nt][0], sacc[nt][1]));
            rm8 = fmaxf(rm8, fmaxf(sacc[nt][2], sacc[nt][3]));
        }
#pragma unroll
        for (int o = 1; o <= 2; o <<= 1) {
            rm0 = fmaxf(rm0, __shfl_xor_sync(0xffffffffu, rm0, o));
            rm8 = fmaxf(rm8, __shfl_xor_sync(0xffffffffu, rm8, o));
        }
        float mn0 = fmaxf(m0, rm0), mn8 = fmaxf(m8, rm8);
        float fs0 = ex2f(m0 - mn0), fs8 = ex2f(m8 - mn8);
        float rs0 = 0.0f, rs8 = 0.0f;
#pragma unroll
        for (int nt = 0; nt < 8; nt++) {
            sacc[nt][0] = ex2f(sacc[nt][0] - mn0);
            sacc[nt][1] = ex2f(sacc[nt][1] - mn0);
            sacc[nt][2] = ex2f(sacc[nt][2] - mn8);
            sacc[nt][3] = ex2f(sacc[nt][3] - mn8);
            rs0 += sacc[nt][0] + sacc[nt][1];
            rs8 += sacc[nt][2] + sacc[nt][3];
        }
#pragma unroll
        for (int o = 1; o <= 2; o <<= 1) {
            rs0 += __shfl_xor_sync(0xffffffffu, rs0, o);
            rs8 += __shfl_xor_sync(0xffffffffu, rs8, o);
        }
        m0 = mn0; m8 = mn8;
        l0 = l0 * fs0 + rs0;
        l8 = l8 * fs8 + rs8;
#pragma unroll
        for (int nt = 0; nt < 8; nt++) {
            oacc[nt][0] *= fs0; oacc[nt][1] *= fs0;
            oacc[nt][2] *= fs8; oacc[nt][3] *= fs8;
        }

        // O += P V  (P passes mma->mma in registers)
#pragma unroll
        for (int kt = 0; kt < 4; kt++) {
            uint32_t a[4];
            a[0] = pkbf(sacc[2 * kt][0],     sacc[2 * kt][1]);
            a[1] = pkbf(sacc[2 * kt][2],     sacc[2 * kt][3]);
            a[2] = pkbf(sacc[2 * kt + 1][0], sacc[2 * kt + 1][1]);
            a[3] = pkbf(sacc[2 * kt + 1][2], sacc[2 * kt + 1][3]);
#pragma unroll
            for (int nt = 0; nt < 8; nt++) {
                uint32_t bf[2];
                bf[0] = Vs[(8 * kt + c) * 72 + nt * 8 + g];
                bf[1] = Vs[(8 * kt + c + 4) * 72 + nt * 8 + g];
                mma_bf16(oacc[nt], a, bf);
            }
        }
    }

    // finalize -> bf16
    float inv0 = 1.0f / l0, inv8 = 1.0f / l8;
    size_t row0 = (size_t)(b * Tt + q0 + qr);
#pragma unroll
    for (int nt = 0; nt < 8; nt++) {
        int col = h * DHh + nt * 8 + 2 * c;
        *(uint32_t*)(out + row0 * Dm + col) =
            pkbf(oacc[nt][0] * inv0, oacc[nt][1] * inv0);
        *(uint32_t*)(out + (row0 + 8) * Dm + col) =
            pkbf(oacc[nt][2] * inv8, oacc[nt][3] * inv8);
    }
}

// ---------------- host launcher ----------------
extern "C" void kernel_launch(void* const* d_in, const int* in_sizes, int n_in,
                              void* d_out, int out_size)
{
    const float* x     = (const float*)d_in[0];
    const float* init0 = (const float*)d_in[1];
    const float* init1 = (const float*)d_in[2];
    // d_in[3] = mask : all-true by construction, ignored
    const float* ln1_g = (const float*)d_in[4];
    const float* ln1_b = (const float*)d_in[5];
    const float* qkv_W = (const float*)d_in[6];
    const float* out_W = (const float*)d_in[7];
    const float* out_b = (const float*)d_in[8];
    const float* ln2_g = (const float*)d_in[9];
    const float* ln2_b = (const float*)d_in[10];
    const float* ff_W1 = (const float*)d_in[11];
    const float* ff_b1 = (const float*)d_in[12];
    const float* ff_W2 = (const float*)d_in[13];
    const float* ff_b2 = (const float*)d_in[14];
    const float* ln3_g = (const float*)d_in[15];
    const float* ln3_b = (const float*)d_in[16];
    const float* r0_W1 = (const float*)d_in[17];
    const float* r0_b1 = (const float*)d_in[18];
    const float* r0_W2 = (const float*)d_in[19];
    const float* r0_b2 = (const float*)d_in[20];
    const float* ln4_g = (const float*)d_in[21];
    const float* ln4_b = (const float*)d_in[22];
    const float* r1_W1 = (const float*)d_in[23];
    const float* r1_b1 = (const float*)d_in[24];
    const float* r1_W2 = (const float*)d_in[25];
    const float* r1_b2 = (const float*)d_in[26];
    float* outp = (float*)d_out;

    float *gx, *gy0, *gy1;
    __nv_bfloat16 *gh, *gqkv, *gatt, *gff, *gcat;
    uint32_t* gwp;
    cudaGetSymbolAddress((void**)&gx,   g_x);
    cudaGetSymbolAddress((void**)&gh,   g_h);
    cudaGetSymbolAddress((void**)&gqkv, g_qkv);
    cudaGetSymbolAddress((void**)&gatt, g_att);
    cudaGetSymbolAddress((void**)&gff,  g_ff);
    cudaGetSymbolAddress((void**)&gcat, g_cat);
    cudaGetSymbolAddress((void**)&gy0,  g_y0);
    cudaGetSymbolAddress((void**)&gy1,  g_y1);
    cudaGetSymbolAddress((void**)&gwp,  g_wp);

    // packed-weight layout: per layer 8 entries
    static const int WSZ[8] = {256 * 1536, 256 * 512, 256 * 2048, 1024 * 512,
                               328 * 2048, 1024 * 132, 264 * 2048, 1024 * 3};
    static const int WK[8] = {512, 512, 512, 2048, 644, 2048, 515, 2048};
    static const int WN[8] = {1536, 512, 2048, 512, 2048, 132, 2048, 3};

    PackTab tab;
    int off = 0;
    int wpoff[2][8];
    for (int l = 0; l < 2; l++) {
        const float* srcs[8] = {
            qkv_W + (size_t)l * 512 * 1536, out_W + (size_t)l * 512 * 512,
            ff_W1 + (size_t)l * 512 * 2048, ff_W2 + (size_t)l * 2048 * 512,
            r0_W1 + (size_t)l * 644 * 2048, r0_W2 + (size_t)l * 2048 * 132,
            r1_W1 + (size_t)l * 515 * 2048, r1_W2 + (size_t)l * 2048 * 3};
        for (int e = 0; e < 8; e++) {
            int idx = l * 8 + e;
            tab.src[idx] = srcs[e];
            tab.off[idx] = off;
            tab.Ktrue[idx] = WK[e];
            tab.N[idx] = WN[e];
            wpoff[l][e] = off;
            off += WSZ[e];
        }
    }
    tab.off[16] = off;   // == WPTOT

    pack_kernel<<<2048, 256>>>(tab, off);

    for (int l = 0; l < LAYERS; l++) {
        const float* xres  = l ? gx  : x;
        const float* y0res = l ? gy0 : init0;
        const float* y1res = l ? gy1 : init1;
        float* y0dst = (l == LAYERS - 1) ? outp : gy0;
        float* y1dst = (l == LAYERS - 1) ? outp + ROWS * O0 : gy1;

        // --- attention block ---
        ln_kernel<<<ROWS / 4, 128>>>(xres, ln1_g + l * Dm, ln1_b + l * Dm, gh, Dm);
        gemm_bf16_kernel<<<dim3(QKVW / 128, ROWS / 128), 256>>>(
            gh, Dm, gwp + wpoff[l][0], nullptr, nullptr, nullptr, gqkv, ROWS, QKVW, 0);
        attn_kernel<<<dim3(Tt / 64, Hh, Bb), 128>>>(gqkv, gatt);
        gemm_bf16_kernel<<<dim3(Dm / 128, ROWS / 128), 256>>>(
            gatt, Dm, gwp + wpoff[l][1], out_b + l * Dm, xres, gx, nullptr, ROWS, Dm, 0);
        // --- FFN block ---
        ln_kernel<<<ROWS / 4, 128>>>(gx, ln2_g + l * Dm, ln2_b + l * Dm, gh, Dm);
        gemm_bf16_kernel<<<dim3(Mff / 128, ROWS / 128), 256>>>(
            gh, Dm, gwp + wpoff[l][2], ff_b1 + l * Mff, nullptr, nullptr, gff, ROWS, Mff, 1);
        gemm_bf16_kernel<<<dim3(Dm / 128, ROWS / 128), 256>>>(
            gff, Mff, gwp + wpoff[l][3], ff_b2 + l * Dm, gx, gx, nullptr, ROWS, Dm, 0);
        // --- regressor 0 ---
        ln_kernel<<<ROWS / 4, 128>>>(gx, ln3_g + l * Dm, ln3_b + l * Dm, gcat, CAT0);
        caty_kernel<<<576, 256>>>(y0res, O0, CAT0, gcat, ROWS * (CAT0 - Dm));
        gemm_bf16_kernel<<<dim3(Mff / 128, ROWS / 128), 256>>>(
            gcat, CAT0, gwp + wpoff[l][4], r0_b1 + l * Mff, nullptr, nullptr, gff, ROWS, Mff, 1);
        gemm_bf16_kernel<<<dim3(2, ROWS / 128), 256>>>(
            gff, Mff, gwp + wpoff[l][5], r0_b2 + l * O0, y0res, y0dst, nullptr, ROWS, O0, 0);
        // --- regressor 1 ---
        ln_kernel<<<ROWS / 4, 128>>>(gx, ln4_g + l * Dm, ln4_b + l * Dm, gcat, CAT1);
        caty_kernel<<<64, 256>>>(y1res, O1, CAT1, gcat, ROWS * (CAT1 - Dm));
        gemm_bf16_kernel<<<dim3(Mff / 128, ROWS / 128), 256>>>(
            gcat, CAT1, gwp + wpoff[l][6], r1_b1 + l * Mff, nullptr, nullptr, gff, ROWS, Mff, 1);
        gemm_bf16_kernel<<<dim3(1, ROWS / 128), 256>>>(
            gff, Mff, gwp + wpoff[l][7], r1_b2 + l * O1, y1res, y1dst, nullptr, ROWS, O1, 0);
    }
}

// round 7
// speedup vs baseline: 5.9112x; 1.0592x over previous
#include <cuda_runtime.h>
#include <cuda_bf16.h>
#include <math.h>
#include <stdint.h>

// ---------------- problem constants ----------------
#define LAYERS 2
#define Dm     512
#define Hh     8
#define DHh    64
#define Mff    2048
#define O0     132
#define O1     3
#define Bb     2
#define Tt     2048
#define ROWS   (Bb*Tt)          // 4096
#define QKVW   (3*Hh*DHh)       // 1536
#define CAT0   656              // 644 padded to mult of 16
#define CAT1   528              // 515 padded to mult of 16
#define WPTOT  5847040          // packed-weight u32 count (both layers)
#define KSPLIT 4

// ---------------- scratch (device globals, no allocs) ----------------
__device__ __align__(128) float          g_x  [ROWS * Dm];
__device__ __align__(128) __nv_bfloat16  g_h  [ROWS * Dm];
__device__ __align__(128) __nv_bfloat16  g_qkv[ROWS * QKVW];
__device__ __align__(128) __nv_bfloat16  g_att[ROWS * Dm];
__device__ __align__(128) __nv_bfloat16  g_ff [ROWS * Mff];
__device__ __align__(128) __nv_bfloat16  g_cat[ROWS * CAT0];
__device__ __align__(128) float          g_y0 [ROWS * O0];
__device__ __align__(128) float          g_y1 [ROWS * O1];
__device__ __align__(128) uint32_t       g_wp [WPTOT];
__device__ __align__(128) float          g_part[KSPLIT * ROWS * O0];

// ---------------- helpers ----------------
__device__ __forceinline__ float gelu_exact(float x) {
    return 0.5f * x * (1.0f + erff(x * 0.70710678118654752f));
}
__device__ __forceinline__ uint32_t pkbf(float lo, float hi) {
    uint32_t r;
    asm("cvt.rn.bf16x2.f32 %0, %1, %2;" : "=r"(r) : "f"(hi), "f"(lo));
    return r;
}
__device__ __forceinline__ float ex2f(float x) {
    float r;
    asm("ex2.approx.f32 %0, %1;" : "=f"(r) : "f"(x));
    return r;
}
__device__ __forceinline__ void mma_bf16(float* d, const uint32_t* a, const uint32_t* b) {
    asm volatile("mma.sync.aligned.m16n8k16.row.col.f32.bf16.bf16.f32 "
        "{%0,%1,%2,%3}, {%4,%5,%6,%7}, {%8,%9}, {%0,%1,%2,%3};\n"
        : "+f"(d[0]), "+f"(d[1]), "+f"(d[2]), "+f"(d[3])
        : "r"(a[0]), "r"(a[1]), "r"(a[2]), "r"(a[3]), "r"(b[0]), "r"(b[1]));
}
__device__ __forceinline__ void cp16(void* dst, const void* src) {
    uint32_t d = (uint32_t)__cvta_generic_to_shared(dst);
    asm volatile("cp.async.cg.shared.global [%0], [%1], 16;\n" :: "r"(d), "l"(src));
}
__device__ __forceinline__ void cp4(void* dst, const void* src, bool p) {
    uint32_t d = (uint32_t)__cvta_generic_to_shared(dst);
    int sz = p ? 4 : 0;
    asm volatile("cp.async.ca.shared.global [%0], [%1], 4, %2;\n" :: "r"(d), "l"(src), "r"(sz));
}
__device__ __forceinline__ void cp_commit() { asm volatile("cp.async.commit_group;\n"); }
template <int NN>
__device__ __forceinline__ void cp_wait() { asm volatile("cp.async.wait_group %0;\n" :: "n"(NN)); }

// ---------------- weight pre-pack: fp32 [K][N] -> u32 pairs [Kp2][N] ----------------
struct PackTab {
    const float* src[16];
    int off[17];
    int Ktrue[16];
    int N[16];
};

__global__ void pack_kernel(PackTab t, int total) {
    int stride = gridDim.x * blockDim.x;
    for (int i = blockIdx.x * blockDim.x + threadIdx.x; i < total; i += stride) {
        int e = 0;
        while (e < 15 && i >= t.off[e + 1]) e++;
        int loc = i - t.off[e];
        int N = t.N[e];
        int k2 = loc / N, n = loc - k2 * N;
        const float* s = t.src[e];
        int K = t.Ktrue[e];
        float lo = (2 * k2     < K) ? s[(size_t)(2 * k2)     * N + n] : 0.0f;
        float hi = (2 * k2 + 1 < K) ? s[(size_t)(2 * k2 + 1) * N + n] : 0.0f;
        g_wp[i] = pkbf(lo, hi);
    }
}

// ---------------- layernorm: warp per row, one-pass stats, bf16 out ----------------
__global__ __launch_bounds__(128) void ln_kernel(
    const float* __restrict__ x, const float* __restrict__ g,
    const float* __restrict__ bta, __nv_bfloat16* __restrict__ out, int ldo)
{
    int wid = threadIdx.x >> 5, lane = threadIdx.x & 31;
    int row = blockIdx.x * 4 + wid;
    const float4* xr = (const float4*)(x + (size_t)row * Dm);
    float4 v[4];
    float s1 = 0.0f, s2 = 0.0f;
#pragma unroll
    for (int i = 0; i < 4; i++) {
        v[i] = xr[lane + 32 * i];
        s1 += (v[i].x + v[i].y) + (v[i].z + v[i].w);
        s2 += v[i].x * v[i].x + v[i].y * v[i].y + v[i].z * v[i].z + v[i].w * v[i].w;
    }
#pragma unroll
    for (int o = 16; o; o >>= 1) {
        s1 += __shfl_xor_sync(0xffffffffu, s1, o);
        s2 += __shfl_xor_sync(0xffffffffu, s2, o);
    }
    float mean = s1 * (1.0f / Dm);
    float var  = s2 * (1.0f / Dm) - mean * mean;
    float rstd = rsqrtf(var + 1e-5f);
    const float4* gr = (const float4*)g;
    const float4* br = (const float4*)bta;
    uint32_t* orow = (uint32_t*)(out + (size_t)row * ldo);
#pragma unroll
    for (int i = 0; i < 4; i++) {
        float4 gg = gr[lane + 32 * i];
        float4 bb = br[lane + 32 * i];
        uint2 u;
        u.x = pkbf((v[i].x - mean) * rstd * gg.x + bb.x, (v[i].y - mean) * rstd * gg.y + bb.y);
        u.y = pkbf((v[i].z - mean) * rstd * gg.z + bb.z, (v[i].w - mean) * rstd * gg.w + bb.w);
        *(uint2*)(orow + (lane + 32 * i) * 2) = u;
    }
}

// ---------------- fill y columns + zero pad of concat buffer ----------------
__global__ void caty_kernel(const float* __restrict__ y, int O, int ldc,
                            __nv_bfloat16* __restrict__ out, int total)
{
    int width = ldc - Dm;
    int stride = gridDim.x * blockDim.x;
    for (int i = blockIdx.x * blockDim.x + threadIdx.x; i < total; i += stride) {
        int r = i / width, cc = i - r * width;
        float v = (cc < O) ? y[(size_t)r * O + cc] : 0.0f;
        out[(size_t)r * ldc + Dm + cc] = __float2bfloat16(v);
    }
}

// ---------------- split-K reduce: out = sum(part) + bias + res ----------------
__global__ void redk_kernel(const float* __restrict__ part,
                            const float* __restrict__ bias,
                            const float* __restrict__ res,
                            float* __restrict__ out, int N, int total)
{
    int stride = gridDim.x * blockDim.x;
    for (int i = blockIdx.x * blockDim.x + threadIdx.x; i < total; i += stride) {
        float v = part[i] + part[i + total] + part[i + 2 * total] + part[i + 3 * total];
        v += bias[i % N] + res[i];
        out[i] = v;
    }
}

// ---------------- bf16 tensor-core GEMM ----------------
// C = act(A[M,lda]bf16 @ Wp + bias) [+res];  Wp = pair-packed bf16 [lda/2][N]
// Block 128x128, 256 thr (8 warps 2x4), warp 64x32, mma m16n8k16.
// gridDim.z > 1 => split-K: each z computes lda/z slice into Cf + z*M*N (raw partial).
__global__ __launch_bounds__(256) void gemm_bf16_kernel(
    const __nv_bfloat16* __restrict__ A, int lda,
    const uint32_t* __restrict__ Wp,
    const float* __restrict__ bias,
    const float* __restrict__ res,
    float* __restrict__ Cf,
    __nv_bfloat16* __restrict__ Cb,
    int M, int N, int act)
{
    __shared__ uint32_t As[2][128][20];   // 128 x 16 bf16, pitch 20 words
    __shared__ uint32_t Bs[2][8][136];    // 8 k-pair rows x 128 n, pitch 136

    int tid  = threadIdx.x;
    int lane = tid & 31, wid = tid >> 5;
    int g = lane >> 2, c = lane & 3;
    int wm0 = (wid >> 2) * 64;
    int wn0 = (wid & 3) * 32;
    int m0 = blockIdx.y * 128, n0 = blockIdx.x * 128;

    float acc[4][4][4];
#pragma unroll
    for (int i = 0; i < 4; i++)
#pragma unroll
        for (int j = 0; j < 4; j++)
#pragma unroll
            for (int k = 0; k < 4; k++) acc[i][j][k] = 0.0f;

    int ar = tid >> 1, ak = (tid & 1) * 8;   // bf16 col offset in tile
    int br = tid >> 5, bc = (tid & 31) * 4;

    int tilesAll = lda >> 4;
    int tilesPer = tilesAll / gridDim.z;
    int t0 = blockIdx.z * tilesPer;
    int t1 = t0 + tilesPer;
    if (gridDim.z > 1) Cf += (size_t)blockIdx.z * M * N;

#define LOAD_TILE(t, buf)                                                     \
    {                                                                         \
        const __nv_bfloat16* ap_ = A + (size_t)(m0 + ar) * lda + (t) * 16 + ak;\
        cp16(&As[buf][ar][ak >> 1], ap_);                                     \
        int prow_ = (t) * 8 + br;                                             \
        int gn_ = n0 + bc;                                                    \
        const uint32_t* bp_ = Wp + (size_t)prow_ * N + gn_;                   \
        if (gn_ + 3 < N) {                                                    \
            cp16(&Bs[buf][br][bc], bp_);                                      \
        } else {                                                              \
            _Pragma("unroll")                                                 \
            for (int ii_ = 0; ii_ < 4; ii_++)                                 \
                cp4(&Bs[buf][br][bc + ii_], bp_ + ii_, gn_ + ii_ < N);        \
        }                                                                     \
    }

    LOAD_TILE(t0, 0);
    cp_commit();

    for (int t = t0; t < t1; t++) {
        cp_wait<0>();
        __syncthreads();
        int buf = t & 1;
        if (t + 1 < t1) {
            LOAD_TILE(t + 1, (t + 1) & 1);
            cp_commit();
        }

        uint32_t af[4][4], bfr[4][2];
#pragma unroll
        for (int mt = 0; mt < 4; mt++) {
            int m = wm0 + mt * 16 + g;
            af[mt][0] = As[buf][m][c];
            af[mt][1] = As[buf][m + 8][c];
            af[mt][2] = As[buf][m][c + 4];
            af[mt][3] = As[buf][m + 8][c + 4];
        }
#pragma unroll
        for (int nt = 0; nt < 4; nt++) {
            int n = wn0 + nt * 8 + g;
            bfr[nt][0] = Bs[buf][c][n];
            bfr[nt][1] = Bs[buf][c + 4][n];
        }
#pragma unroll
        for (int mt = 0; mt < 4; mt++)
#pragma unroll
            for (int nt = 0; nt < 4; nt++)
                mma_bf16(acc[mt][nt], af[mt], bfr[nt]);
    }

    // epilogue (vector path only for even N: odd N makes row*N odd ->
    // float2/bf16x2 accesses misaligned)
    bool Neven = (N & 1) == 0;
#pragma unroll
    for (int mt = 0; mt < 4; mt++) {
#pragma unroll
        for (int nt = 0; nt < 4; nt++) {
            int col = n0 + wn0 + nt * 8 + c * 2;
#pragma unroll
            for (int hh = 0; hh < 2; hh++) {
                int row = m0 + wm0 + mt * 16 + g + hh * 8;
                float v0 = acc[mt][nt][hh * 2 + 0];
                float v1 = acc[mt][nt][hh * 2 + 1];
                size_t off = (size_t)row * N + col;
                if (Neven && col + 1 < N) {
                    if (bias) { v0 += bias[col]; v1 += bias[col + 1]; }
                    if (act)  { v0 = gelu_exact(v0); v1 = gelu_exact(v1); }
                    if (res) {
                        float2 rr = *(const float2*)(res + off);
                        v0 += rr.x; v1 += rr.y;
                    }
                    if (Cb) *(uint32_t*)(Cb + off) = pkbf(v0, v1);
                    else    *(float2*)(Cf + off) = make_float2(v0, v1);
                } else {
                    if (col < N) {
                        if (bias) v0 += bias[col];
                        if (act)  v0 = gelu_exact(v0);
                        if (res)  v0 += res[off];
                        if (Cb) Cb[off] = __float2bfloat16(v0);
                        else    Cf[off] = v0;
                    }
                    if (col + 1 < N) {
                        if (bias) v1 += bias[col + 1];
                        if (act)  v1 = gelu_exact(v1);
                        if (res)  v1 += res[off + 1];
                        if (Cb) Cb[off + 1] = __float2bfloat16(v1);
                        else    Cf[off + 1] = v1;
                    }
                }
            }
        }
    }
#undef LOAD_TILE
}

// ---------------- bf16 tensor-core flash attention ----------------
// Block: 128 queries, 256 threads (8 warps). qkv bf16 [ROWS,1536], out bf16 [ROWS,512]
__global__ __launch_bounds__(256) void attn_kernel(
    const __nv_bfloat16* __restrict__ qkv, __nv_bfloat16* __restrict__ out)
{
    __shared__ uint32_t Qs[128 * 20];  // 128 x 64 bf16, pitch 20 words
    __shared__ uint32_t Ks[64 * 20];
    __shared__ uint32_t Vs[32 * 72];   // 32 j-pair rows x 64 d, pitch 72

    int tid  = threadIdx.x;
    int lane = tid & 31, w = tid >> 5;
    int g = lane >> 2, c = lane & 3;
    int q0 = blockIdx.x * 128;
    int h  = blockIdx.y;
    int b  = blockIdx.z;

    const __nv_bfloat16* base = qkv + (size_t)b * Tt * QKVW;
    const float qscale = 0.125f * 1.4426950408889634f;  // DH^-.5 * log2(e)

    // load Q tile, fold scale, keep bf16
#pragma unroll
    for (int it = 0; it < 4; it++) {
        int f = tid + it * 256;       // 1024 uint4 chunks
        int r = f >> 3;
        int seg = f & 7;
        uint4 q = *(const uint4*)(base + (size_t)(q0 + r) * QKVW + h * DHh + seg * 8);
        uint32_t* qw = &q.x;
        uint32_t o[4];
#pragma unroll
        for (int t = 0; t < 4; t++) {
            float lo = __uint_as_float(qw[t] << 16) * qscale;
            float hi = __uint_as_float(qw[t] & 0xFFFF0000u) * qscale;
            o[t] = pkbf(lo, hi);
        }
        *(uint4*)&Qs[r * 20 + seg * 4] = make_uint4(o[0], o[1], o[2], o[3]);
    }

    float oacc[8][4];
#pragma unroll
    for (int i = 0; i < 8; i++)
#pragma unroll
        for (int j = 0; j < 4; j++) oacc[i][j] = 0.0f;
    float m0 = -1e30f, m8 = -1e30f, l0 = 0.0f, l8 = 0.0f;
    int qr = w * 16 + g;

    for (int jt = 0; jt < Tt; jt += 64) {
        __syncthreads();
        // K: straight copy (512 uint4)
#pragma unroll
        for (int it = 0; it < 2; it++) {
            int f = tid + it * 256;
            int r = f >> 3;
            int seg = f & 7;
            *(uint4*)&Ks[r * 20 + seg * 4] =
                *(const uint4*)(base + (size_t)(jt + r) * QKVW + Hh * DHh + h * DHh + seg * 8);
        }
        // V: pair-interleave rows 2j2/2j2+1 (256 chunks)
        {
            int f = tid;
            int j2 = f >> 3;
            int dc = f & 7;
            const uint32_t* pa = (const uint32_t*)(base + (size_t)(jt + 2 * j2) * QKVW
                                                   + 2 * Hh * DHh + h * DHh + dc * 8);
            const uint32_t* pb = pa + (QKVW / 2);
            uint4 va = *(const uint4*)pa;
            uint4 vb = *(const uint4*)pb;
            const uint32_t* au = &va.x;
            const uint32_t* bu = &vb.x;
            uint32_t o[8];
#pragma unroll
            for (int t = 0; t < 4; t++) {
                o[2 * t + 0] = (au[t] & 0x0000FFFFu) | (bu[t] << 16);
                o[2 * t + 1] = (au[t] >> 16) | (bu[t] & 0xFFFF0000u);
            }
            uint32_t* dst = &Vs[j2 * 72 + dc * 8];
            *(uint4*)dst       = make_uint4(o[0], o[1], o[2], o[3]);
            *(uint4*)(dst + 4) = make_uint4(o[4], o[5], o[6], o[7]);
        }
        __syncthreads();

        // S = Q K^T (log2-scaled)
        float sacc[8][4];
#pragma unroll
        for (int i = 0; i < 8; i++)
#pragma unroll
            for (int j = 0; j < 4; j++) sacc[i][j] = 0.0f;
#pragma unroll
        for (int kt = 0; kt < 4; kt++) {
            uint32_t a[4];
            a[0] = Qs[qr * 20 + 8 * kt + c];
            a[1] = Qs[(qr + 8) * 20 + 8 * kt + c];
            a[2] = Qs[qr * 20 + 8 * kt + c + 4];
            a[3] = Qs[(qr + 8) * 20 + 8 * kt + c + 4];
#pragma unroll
            for (int nt = 0; nt < 8; nt++) {
                uint32_t bf[2];
                bf[0] = Ks[(nt * 8 + g) * 20 + 8 * kt + c];
                bf[1] = Ks[(nt * 8 + g) * 20 + 8 * kt + c + 4];
                mma_bf16(sacc[nt], a, bf);
            }
        }

        // online softmax in base-2
        float rm0 = -1e30f, rm8 = -1e30f;
#pragma unroll
        for (int nt = 0; nt < 8; nt++) {
            rm0 = fmaxf(rm0, fmaxf(sacc[nt][0], sacc[nt][1]));
            rm8 = fmaxf(rm8, fmaxf(sacc[nt][2], sacc[nt][3]));
        }
#pragma unroll
        for (int o = 1; o <= 2; o <<= 1) {
            rm0 = fmaxf(rm0, __shfl_xor_sync(0xffffffffu, rm0, o));
            rm8 = fmaxf(rm8, __shfl_xor_sync(0xffffffffu, rm8, o));
        }
        float mn0 = fmaxf(m0, rm0), mn8 = fmaxf(m8, rm8);
        float fs0 = ex2f(m0 - mn0), fs8 = ex2f(m8 - mn8);
        float rs0 = 0.0f, rs8 = 0.0f;
#pragma unroll
        for (int nt = 0; nt < 8; nt++) {
            sacc[nt][0] = ex2f(sacc[nt][0] - mn0);
            sacc[nt][1] = ex2f(sacc[nt][1] - mn0);
            sacc[nt][2] = ex2f(sacc[nt][2] - mn8);
            sacc[nt][3] = ex2f(sacc[nt][3] - mn8);
            rs0 += sacc[nt][0] + sacc[nt][1];
            rs8 += sacc[nt][2] + sacc[nt][3];
        }
#pragma unroll
        for (int o = 1; o <= 2; o <<= 1) {
            rs0 += __shfl_xor_sync(0xffffffffu, rs0, o);
            rs8 += __shfl_xor_sync(0xffffffffu, rs8, o);
        }
        m0 = mn0; m8 = mn8;
        l0 = l0 * fs0 + rs0;
        l8 = l8 * fs8 + rs8;
#pragma unroll
        for (int nt = 0; nt < 8; nt++) {
            oacc[nt][0] *= fs0; oacc[nt][1] *= fs0;
            oacc[nt][2] *= fs8; oacc[nt][3] *= fs8;
        }

        // O += P V  (P passes mma->mma in registers)
#pragma unroll
        for (int kt = 0; kt < 4; kt++) {
            uint32_t a[4];
            a[0] = pkbf(sacc[2 * kt][0],     sacc[2 * kt][1]);
            a[1] = pkbf(sacc[2 * kt][2],     sacc[2 * kt][3]);
            a[2] = pkbf(sacc[2 * kt + 1][0], sacc[2 * kt + 1][1]);
            a[3] = pkbf(sacc[2 * kt + 1][2], sacc[2 * kt + 1][3]);
#pragma unroll
            for (int nt = 0; nt < 8; nt++) {
                uint32_t bf[2];
                bf[0] = Vs[(8 * kt + c) * 72 + nt * 8 + g];
                bf[1] = Vs[(8 * kt + c + 4) * 72 + nt * 8 + g];
                mma_bf16(oacc[nt], a, bf);
            }
        }
    }

    // finalize -> bf16
    float inv0 = 1.0f / l0, inv8 = 1.0f / l8;
    size_t row0 = (size_t)(b * Tt + q0 + qr);
#pragma unroll
    for (int nt = 0; nt < 8; nt++) {
        int col = h * DHh + nt * 8 + 2 * c;
        *(uint32_t*)(out + row0 * Dm + col) =
            pkbf(oacc[nt][0] * inv0, oacc[nt][1] * inv0);
        *(uint32_t*)(out + (row0 + 8) * Dm + col) =
            pkbf(oacc[nt][2] * inv8, oacc[nt][3] * inv8);
    }
}

// ---------------- host launcher ----------------
extern "C" void kernel_launch(void* const* d_in, const int* in_sizes, int n_in,
                              void* d_out, int out_size)
{
    const float* x     = (const float*)d_in[0];
    const float* init0 = (const float*)d_in[1];
    const float* init1 = (const float*)d_in[2];
    // d_in[3] = mask : all-true by construction, ignored
    const float* ln1_g = (const float*)d_in[4];
    const float* ln1_b = (const float*)d_in[5];
    const float* qkv_W = (const float*)d_in[6];
    const float* out_W = (const float*)d_in[7];
    const float* out_b = (const float*)d_in[8];
    const float* ln2_g = (const float*)d_in[9];
    const float* ln2_b = (const float*)d_in[10];
    const float* ff_W1 = (const float*)d_in[11];
    const float* ff_b1 = (const float*)d_in[12];
    const float* ff_W2 = (const float*)d_in[13];
    const float* ff_b2 = (const float*)d_in[14];
    const float* ln3_g = (const float*)d_in[15];
    const float* ln3_b = (const float*)d_in[16];
    const float* r0_W1 = (const float*)d_in[17];
    const float* r0_b1 = (const float*)d_in[18];
    const float* r0_W2 = (const float*)d_in[19];
    const float* r0_b2 = (const float*)d_in[20];
    const float* ln4_g = (const float*)d_in[21];
    const float* ln4_b = (const float*)d_in[22];
    const float* r1_W1 = (const float*)d_in[23];
    const float* r1_b1 = (const float*)d_in[24];
    const float* r1_W2 = (const float*)d_in[25];
    const float* r1_b2 = (const float*)d_in[26];
    float* outp = (float*)d_out;

    float *gx, *gy0, *gy1, *gpart;
    __nv_bfloat16 *gh, *gqkv, *gatt, *gff, *gcat;
    uint32_t* gwp;
    cudaGetSymbolAddress((void**)&gx,    g_x);
    cudaGetSymbolAddress((void**)&gh,    g_h);
    cudaGetSymbolAddress((void**)&gqkv,  g_qkv);
    cudaGetSymbolAddress((void**)&gatt,  g_att);
    cudaGetSymbolAddress((void**)&gff,   g_ff);
    cudaGetSymbolAddress((void**)&gcat,  g_cat);
    cudaGetSymbolAddress((void**)&gy0,   g_y0);
    cudaGetSymbolAddress((void**)&gy1,   g_y1);
    cudaGetSymbolAddress((void**)&gwp,   g_wp);
    cudaGetSymbolAddress((void**)&gpart, g_part);

    // packed-weight layout: per layer 8 entries
    static const int WSZ[8] = {256 * 1536, 256 * 512, 256 * 2048, 1024 * 512,
                               328 * 2048, 1024 * 132, 264 * 2048, 1024 * 3};
    static const int WK[8] = {512, 512, 512, 2048, 644, 2048, 515, 2048};
    static const int WN[8] = {1536, 512, 2048, 512, 2048, 132, 2048, 3};

    PackTab tab;
    int off = 0;
    int wpoff[2][8];
    for (int l = 0; l < 2; l++) {
        const float* srcs[8] = {
            qkv_W + (size_t)l * 512 * 1536, out_W + (size_t)l * 512 * 512,
            ff_W1 + (size_t)l * 512 * 2048, ff_W2 + (size_t)l * 2048 * 512,
            r0_W1 + (size_t)l * 644 * 2048, r0_W2 + (size_t)l * 2048 * 132,
            r1_W1 + (size_t)l * 515 * 2048, r1_W2 + (size_t)l * 2048 * 3};
        for (int e = 0; e < 8; e++) {
            int idx = l * 8 + e;
            tab.src[idx] = srcs[e];
            tab.off[idx] = off;
            tab.Ktrue[idx] = WK[e];
            tab.N[idx] = WN[e];
            wpoff[l][e] = off;
            off += WSZ[e];
        }
    }
    tab.off[16] = off;   // == WPTOT

    pack_kernel<<<2048, 256>>>(tab, off);

    for (int l = 0; l < LAYERS; l++) {
        const float* xres  = l ? gx  : x;
        const float* y0res = l ? gy0 : init0;
        const float* y1res = l ? gy1 : init1;
        float* y0dst = (l == LAYERS - 1) ? outp : gy0;
        float* y1dst = (l == LAYERS - 1) ? outp + ROWS * O0 : gy1;

        // --- attention block ---
        ln_kernel<<<ROWS / 4, 128>>>(xres, ln1_g + l * Dm, ln1_b + l * Dm, gh, Dm);
        gemm_bf16_kernel<<<dim3(QKVW / 128, ROWS / 128), 256>>>(
            gh, Dm, gwp + wpoff[l][0], nullptr, nullptr, nullptr, gqkv, ROWS, QKVW, 0);
        attn_kernel<<<dim3(Tt / 128, Hh, Bb), 256>>>(gqkv, gatt);
        gemm_bf16_kernel<<<dim3(Dm / 128, ROWS / 128), 256>>>(
            gatt, Dm, gwp + wpoff[l][1], out_b + l * Dm, xres, gx, nullptr, ROWS, Dm, 0);
        // --- FFN block ---
        ln_kernel<<<ROWS / 4, 128>>>(gx, ln2_g + l * Dm, ln2_b + l * Dm, gh, Dm);
        gemm_bf16_kernel<<<dim3(Mff / 128, ROWS / 128), 256>>>(
            gh, Dm, gwp + wpoff[l][2], ff_b1 + l * Mff, nullptr, nullptr, gff, ROWS, Mff, 1);
        gemm_bf16_kernel<<<dim3(Dm / 128, ROWS / 128), 256>>>(
            gff, Mff, gwp + wpoff[l][3], ff_b2 + l * Dm, gx, gx, nullptr, ROWS, Dm, 0);
        // --- regressor 0 ---
        ln_kernel<<<ROWS / 4, 128>>>(gx, ln3_g + l * Dm, ln3_b + l * Dm, gcat, CAT0);
        caty_kernel<<<576, 256>>>(y0res, O0, CAT0, gcat, ROWS * (CAT0 - Dm));
        gemm_bf16_kernel<<<dim3(Mff / 128, ROWS / 128), 256>>>(
            gcat, CAT0, gwp + wpoff[l][4], r0_b1 + l * Mff, nullptr, nullptr, gff, ROWS, Mff, 1);
        gemm_bf16_kernel<<<dim3(2, ROWS / 128, KSPLIT), 256>>>(
            gff, Mff, gwp + wpoff[l][5], nullptr, nullptr, gpart, nullptr, ROWS, O0, 0);
        redk_kernel<<<1056, 256>>>(gpart, r0_b2 + l * O0, y0res, y0dst, O0, ROWS * O0);
        // --- regressor 1 ---
        ln_kernel<<<ROWS / 4, 128>>>(gx, ln4_g + l * Dm, ln4_b + l * Dm, gcat, CAT1);
        caty_kernel<<<64, 256>>>(y1res, O1, CAT1, gcat, ROWS * (CAT1 - Dm));
        gemm_bf16_kernel<<<dim3(Mff / 128, ROWS / 128), 256>>>(
            gcat, CAT1, gwp + wpoff[l][6], r1_b1 + l * Mff, nullptr, nullptr, gff, ROWS, Mff, 1);
        gemm_bf16_kernel<<<dim3(1, ROWS / 128, KSPLIT), 256>>>(
            gff, Mff, gwp + wpoff[l][7], nullptr, nullptr, gpart, nullptr, ROWS, O1, 0);
        redk_kernel<<<24, 256>>>(gpart, r1_b2 + l * O1, y1res, y1dst, O1, ROWS * O1);
    }
}